// round 2
// baseline (speedup 1.0000x reference)
#include <cuda_runtime.h>
#include <cuda_bf16.h>

// ---------------------------------------------------------------------------
// GNNTransductiveEdgeHead:
//   h = relu(x @ W1 + b1); h = relu(h @ W2 + b2)
//   pred[e] = dot(h[src[e]], h[dst[e]])
// Inputs (metadata order) — NOTE: JAX default x64-disabled => int32 indices:
//   0: x          float32 [N, 128]
//   1: edge_index int32   [2, E]
//   2: edge_label int32   [E]
//   3: W1 float32 [128,128]   4: b1 float32 [128]
//   5: W2 float32 [128,128]   6: b2 float32 [128]
// Output: pred float32 [E] (plus labels as float if out_size >= 2E)
// ---------------------------------------------------------------------------

#define DD 128
#define MAX_NODES 100000

// Scratch: device globals (runtime allocation is forbidden).
__device__ float g_h1[MAX_NODES * DD];
__device__ float g_h2[MAX_NODES * DD];

// ---------------------------------------------------------------------------
// Fused GEMM + bias + ReLU:  H[N,128] = relu(X[N,128] @ W[128,128] + b)
// Block: 256 threads (16x16), tile 64 rows x 128 cols, thread tile 4x8.
// ---------------------------------------------------------------------------
__global__ void __launch_bounds__(256) mlp_layer_kernel(
    const float* __restrict__ X,
    const float* __restrict__ W,
    const float* __restrict__ B,
    float* __restrict__ H,
    int N)
{
    __shared__ __align__(16) float sW[64][128];  // [k][j]   32 KB
    __shared__ __align__(16) float sX[64][64];   // [row][k] 16 KB

    const int t  = threadIdx.x;
    const int tx = t & 15;        // cols tx*8 .. tx*8+7
    const int ty = t >> 4;        // rows ty*4 .. ty*4+3
    const int row0 = blockIdx.x * 64;

    float acc[4][8];
#pragma unroll
    for (int r = 0; r < 4; r++)
#pragma unroll
        for (int c = 0; c < 8; c++) acc[r][c] = 0.f;

#pragma unroll
    for (int kc = 0; kc < DD; kc += 64) {
        // W chunk: 64 x 128 floats = 2048 float4, 8 per thread.
#pragma unroll
        for (int i = 0; i < 8; i++) {
            int idx = t + i * 256;
            int k   = idx >> 5;
            int j4  = idx & 31;
            *(float4*)&sW[k][j4 * 4] =
                *(const float4*)&W[(kc + k) * DD + j4 * 4];
        }
        // X chunk: 64 rows x 64 floats = 1024 float4, 4 per thread.
#pragma unroll
        for (int i = 0; i < 4; i++) {
            int idx = t + i * 256;
            int r   = idx >> 4;
            int k4  = idx & 15;
            int grow = row0 + r;
            float4 v = make_float4(0.f, 0.f, 0.f, 0.f);
            if (grow < N)
                v = *(const float4*)&X[grow * DD + kc + k4 * 4];
            *(float4*)&sX[r][k4 * 4] = v;
        }
        __syncthreads();

#pragma unroll
        for (int k = 0; k < 64; k++) {
            float xr[4], wj[8];
#pragma unroll
            for (int r = 0; r < 4; r++) xr[r] = sX[ty * 4 + r][k];
#pragma unroll
            for (int c = 0; c < 8; c++) wj[c] = sW[k][tx * 8 + c];
#pragma unroll
            for (int r = 0; r < 4; r++)
#pragma unroll
                for (int c = 0; c < 8; c++)
                    acc[r][c] = fmaf(xr[r], wj[c], acc[r][c]);
        }
        __syncthreads();
    }

#pragma unroll
    for (int r = 0; r < 4; r++) {
        int grow = row0 + ty * 4 + r;
        if (grow < N) {
#pragma unroll
            for (int c = 0; c < 8; c++) {
                int j = tx * 8 + c;
                float v = acc[r][c] + B[j];
                acc[r][c] = v > 0.f ? v : 0.f;
            }
            *(float4*)&H[grow * DD + tx * 8]     = *(float4*)&acc[r][0];
            *(float4*)&H[grow * DD + tx * 8 + 4] = *(float4*)&acc[r][4];
        }
    }
}

// ---------------------------------------------------------------------------
// Edge decode: one warp per edge, 128 dims = 32 lanes x float4, butterfly sum.
// edge_index is int32 (JAX x64 disabled). Clamp defensively: a bad index
// shows up as rel_err, not a crash.
// ---------------------------------------------------------------------------
__global__ void __launch_bounds__(256) edge_dot_kernel(
    const float* __restrict__ H,
    const int* __restrict__ edge_index,
    float* __restrict__ out,
    int E, int N)
{
    int gwarp = (blockIdx.x * blockDim.x + threadIdx.x) >> 5;
    int lane  = threadIdx.x & 31;
    if (gwarp >= E) return;

    int s = edge_index[gwarp];
    int d = edge_index[E + gwarp];
    s = min(max(s, 0), N - 1);
    d = min(max(d, 0), N - 1);

    const float4* a = (const float4*)(H + (long long)s * DD);
    const float4* b = (const float4*)(H + (long long)d * DD);
    float4 av = a[lane];
    float4 bv = b[lane];
    float sum = av.x * bv.x + av.y * bv.y + av.z * bv.z + av.w * bv.w;

#pragma unroll
    for (int o = 16; o > 0; o >>= 1)
        sum += __shfl_xor_sync(0xFFFFFFFFu, sum, o);

    if (lane == 0) out[gwarp] = sum;
}

// ---------------------------------------------------------------------------
// Label passthrough (int32 -> float32), only if out_size covers it.
// ---------------------------------------------------------------------------
__global__ void label_copy_kernel(const int* __restrict__ lbl,
                                  float* __restrict__ out, int E)
{
    int i = blockIdx.x * blockDim.x + threadIdx.x;
    if (i < E) out[i] = (float)lbl[i];
}

extern "C" void kernel_launch(void* const* d_in, const int* in_sizes, int n_in,
                              void* d_out, int out_size)
{
    const float* x   = (const float*)d_in[0];
    const int*   ei  = (const int*)d_in[1];
    const int*   lbl = (const int*)d_in[2];
    const float* W1  = (const float*)d_in[3];
    const float* b1  = (const float*)d_in[4];
    const float* W2  = (const float*)d_in[5];
    const float* b2  = (const float*)d_in[6];

    int N = in_sizes[0] / DD;        // 100000
    int E = in_sizes[2];             // 500000

    float* h1 = nullptr;
    float* h2 = nullptr;
    cudaGetSymbolAddress((void**)&h1, g_h1);
    cudaGetSymbolAddress((void**)&h2, g_h2);

    float* out = (float*)d_out;

    int gemm_blocks = (N + 63) / 64;
    mlp_layer_kernel<<<gemm_blocks, 256>>>(x,  W1, b1, h1, N);
    mlp_layer_kernel<<<gemm_blocks, 256>>>(h1, W2, b2, h2, N);

    int dot_blocks = (E + 7) / 8;    // 8 warps per 256-thread block
    edge_dot_kernel<<<dot_blocks, 256>>>(h2, ei, out, E, N);

    if (out_size >= 2 * E) {
        int lb = (E + 255) / 256;
        label_copy_kernel<<<lb, 256>>>(lbl, out + E, E);
    }
}

// round 4
// speedup vs baseline: 1.5006x; 1.5006x over previous
#include <cuda_runtime.h>
#include <cuda_bf16.h>
#include <cstdint>

// ---------------------------------------------------------------------------
// GNNTransductiveEdgeHead via legacy tensor-core path (mma.sync / HMMA):
//   h = relu(x @ W1 + b1); h = relu(h @ W2 + b2); pred[e]=dot(h[src],h[dst])
// Split-bf16 3-term GEMM for fp32-class accuracy:
//   X@W ~= Xhi@Whi + Xlo@Whi + Xhi@Wlo   (fp32 accumulate, residual ~4e-6)
// NOTE: harness PTX target is plain sm_103 (no 'a') -> tcgen05 unavailable;
// mma.sync.m16n8k16 bf16 + ldmatrix is the supported tensor path.
// Inputs: 0:x f32[N,128] 1:edge_index i32[2,E] 2:edge_label i32[E]
//         3:W1 f32[128,128] 4:b1 f32[128] 5:W2 f32[128,128] 6:b2 f32[128]
// ---------------------------------------------------------------------------

#define DD 128
#define TILE_M 128
#define MAX_NODES 100000

// SMEM layout (bytes). Rows padded to 136 bf16 = 272 B (conflict-free ldmatrix).
#define S_ROW   272
#define A_HI_OFF 0
#define A_LO_OFF 34816
#define B_HI_OFF 69632
#define B_LO_OFF 104448
#define BIAS_OFF 139264
#define SMEM_TOTAL (BIAS_OFF + 512)

// Device-global scratch (no runtime allocation allowed).
__device__ float g_h1[MAX_NODES * DD];
__device__ float g_h2[MAX_NODES * DD];
__device__ __nv_bfloat16 g_w1hi[DD * DD];
__device__ __nv_bfloat16 g_w1lo[DD * DD];
__device__ __nv_bfloat16 g_w2hi[DD * DD];
__device__ __nv_bfloat16 g_w2lo[DD * DD];

__device__ __forceinline__ uint32_t smem_u32(const void* p) {
    uint32_t a;
    asm("{ .reg .u64 t; cvta.to.shared.u64 t, %1; cvt.u32.u64 %0, t; }"
        : "=r"(a) : "l"(p));
    return a;
}

__device__ __forceinline__ void ldmatrix_x4(uint32_t& r0, uint32_t& r1,
                                            uint32_t& r2, uint32_t& r3,
                                            uint32_t addr) {
    asm volatile("ldmatrix.sync.aligned.m8n8.x4.shared.b16 {%0,%1,%2,%3}, [%4];"
                 : "=r"(r0), "=r"(r1), "=r"(r2), "=r"(r3) : "r"(addr));
}
__device__ __forceinline__ void ldmatrix_x4_trans(uint32_t& r0, uint32_t& r1,
                                                  uint32_t& r2, uint32_t& r3,
                                                  uint32_t addr) {
    asm volatile("ldmatrix.sync.aligned.m8n8.x4.trans.shared.b16 {%0,%1,%2,%3}, [%4];"
                 : "=r"(r0), "=r"(r1), "=r"(r2), "=r"(r3) : "r"(addr));
}
__device__ __forceinline__ void mma_bf16(float* c, uint32_t a0, uint32_t a1,
                                         uint32_t a2, uint32_t a3,
                                         uint32_t b0, uint32_t b1) {
    asm volatile(
        "mma.sync.aligned.m16n8k16.row.col.f32.bf16.bf16.f32 "
        "{%0,%1,%2,%3}, {%4,%5,%6,%7}, {%8,%9}, {%0,%1,%2,%3};"
        : "+f"(c[0]), "+f"(c[1]), "+f"(c[2]), "+f"(c[3])
        : "r"(a0), "r"(a1), "r"(a2), "r"(a3), "r"(b0), "r"(b1));
}

// ---------------------------------------------------------------------------
// W prep: split W (fp32 [k][n]) into bf16 hi/lo, same [k][n] layout.
// ---------------------------------------------------------------------------
__global__ void wprep_kernel(const float* __restrict__ W,
                             __nv_bfloat16* __restrict__ hi,
                             __nv_bfloat16* __restrict__ lo) {
    int i = blockIdx.x * blockDim.x + threadIdx.x;
    if (i >= DD * DD) return;
    float w = W[i];
    __nv_bfloat16 h = __float2bfloat16_rn(w);
    hi[i] = h;
    lo[i] = __float2bfloat16_rn(w - __bfloat162float(h));
}

// ---------------------------------------------------------------------------
// Fused layer: H[N,128] = relu(X[N,128] @ W + b), mma.sync split-bf16.
// 256 threads / 8 warps; warp w computes rows [16w, 16w+16) x 128 cols.
// ---------------------------------------------------------------------------
__global__ void __launch_bounds__(256) mlp_mma_kernel(
    const float* __restrict__ X,
    const __nv_bfloat16* __restrict__ Whi,
    const __nv_bfloat16* __restrict__ Wlo,
    const float* __restrict__ bias,
    float* __restrict__ H,
    int N)
{
    extern __shared__ __align__(16) char smem[];
    const uint32_t sb = smem_u32(smem);

    const int tid  = threadIdx.x;
    const int warp = tid >> 5;
    const int lane = tid & 31;
    const int row0 = blockIdx.x * TILE_M;

    // Bias -> smem
    if (tid < DD) ((float*)(smem + BIAS_OFF))[tid] = bias[tid];

    // --- X load + hi/lo split. Thread handles row tid/2, 64-col half. ---
    {
        const int row  = tid >> 1;
        const int half = (tid & 1) * 64;
        const int grow = row0 + row;
        const bool ok = grow < N;
        const float4* src = (const float4*)(X + (long long)grow * DD + half);
        char* dhi = smem + A_HI_OFF + row * S_ROW + half * 2;
        char* dlo = smem + A_LO_OFF + row * S_ROW + half * 2;
#pragma unroll
        for (int c0 = 0; c0 < 64; c0 += 8) {
            float4 a, b;
            if (ok) { a = src[c0 >> 2]; b = src[(c0 >> 2) + 1]; }
            else    { a = make_float4(0, 0, 0, 0); b = a; }
            const float v[8] = {a.x, a.y, a.z, a.w, b.x, b.y, b.z, b.w};
            uint32_t hi4[4], lo4[4];
#pragma unroll
            for (int p = 0; p < 4; p++) {
                __nv_bfloat162 h, l;
                h.x = __float2bfloat16_rn(v[2 * p]);
                h.y = __float2bfloat16_rn(v[2 * p + 1]);
                l.x = __float2bfloat16_rn(v[2 * p]     - __bfloat162float(h.x));
                l.y = __float2bfloat16_rn(v[2 * p + 1] - __bfloat162float(h.y));
                hi4[p] = *(uint32_t*)&h;
                lo4[p] = *(uint32_t*)&l;
            }
            *(uint4*)(dhi + c0 * 2) = make_uint4(hi4[0], hi4[1], hi4[2], hi4[3]);
            *(uint4*)(dlo + c0 * 2) = make_uint4(lo4[0], lo4[1], lo4[2], lo4[3]);
        }
    }
    // --- W hi/lo -> smem ([k][n], padded rows) ---
    {
        const int row  = tid >> 1;
        const int half = (tid & 1) * 64;
        const uint4* sh = (const uint4*)(Whi + row * DD + half);
        const uint4* sl = (const uint4*)(Wlo + row * DD + half);
        uint4* dh = (uint4*)(smem + B_HI_OFF + row * S_ROW + half * 2);
        uint4* dl = (uint4*)(smem + B_LO_OFF + row * S_ROW + half * 2);
#pragma unroll
        for (int q = 0; q < 8; q++) { dh[q] = sh[q]; dl[q] = sl[q]; }
    }
    __syncthreads();

    // --- Main MMA loop ---
    float acc[16][4];
#pragma unroll
    for (int n = 0; n < 16; n++)
#pragma unroll
        for (int c = 0; c < 4; c++) acc[n][c] = 0.f;

    const int mw = warp * 16;
    // A addr: row (mw + lane%16), k byte offset ((lane>>4)*8)*2
    const uint32_t a_off = (uint32_t)((mw + (lane & 15)) * S_ROW + (lane >> 4) * 16);
    // B addr: row k (lane%16), n byte offset ((lane>>4)*8)*2
    const uint32_t b_off = (uint32_t)((lane & 15) * S_ROW + (lane >> 4) * 16);

    const uint32_t a_bases[3] = {sb + A_HI_OFF + a_off, sb + A_LO_OFF + a_off,
                                 sb + A_HI_OFF + a_off};
    const uint32_t b_bases[3] = {sb + B_HI_OFF + b_off, sb + B_HI_OFF + b_off,
                                 sb + B_LO_OFF + b_off};

#pragma unroll
    for (int t = 0; t < 3; t++) {
        const uint32_t ab = a_bases[t];
        const uint32_t bb = b_bases[t];
#pragma unroll
        for (int ks = 0; ks < 8; ks++) {
            uint32_t a0, a1, a2, a3;
            ldmatrix_x4(a0, a1, a2, a3, ab + ks * 32);        // k0*2 bytes
            const uint32_t bk = bb + ks * (16 * S_ROW);       // k rows advance
#pragma unroll
            for (int np = 0; np < 8; np++) {
                uint32_t b0, b1, b2, b3;
                ldmatrix_x4_trans(b0, b1, b2, b3, bk + np * 32);  // 16 n per load
                mma_bf16(acc[2 * np],     a0, a1, a2, a3, b0, b1);
                mma_bf16(acc[2 * np + 1], a0, a1, a2, a3, b2, b3);
            }
        }
    }

    // --- Epilogue: bias + relu + store (float2 per row-pair per ntile) ---
    {
        const float* sBias = (const float*)(smem + BIAS_OFF);
        const int r0 = row0 + mw + (lane >> 2);
        const int r1 = r0 + 8;
        float* p0 = H + (long long)r0 * DD;
        float* p1 = H + (long long)r1 * DD;
        const bool ok0 = r0 < N, ok1 = r1 < N;
#pragma unroll
        for (int nt = 0; nt < 16; nt++) {
            const int col = nt * 8 + (lane & 3) * 2;
            const float bx = sBias[col], by = sBias[col + 1];
            if (ok0) {
                float2 v;
                v.x = fmaxf(acc[nt][0] + bx, 0.f);
                v.y = fmaxf(acc[nt][1] + by, 0.f);
                *(float2*)(p0 + col) = v;
            }
            if (ok1) {
                float2 v;
                v.x = fmaxf(acc[nt][2] + bx, 0.f);
                v.y = fmaxf(acc[nt][3] + by, 0.f);
                *(float2*)(p1 + col) = v;
            }
        }
    }
}

// ---------------------------------------------------------------------------
// Edge decode: one warp per edge, 128 dims = 32 lanes x float4, butterfly sum.
// ---------------------------------------------------------------------------
__global__ void __launch_bounds__(256) edge_dot_kernel(
    const float* __restrict__ H,
    const int* __restrict__ edge_index,
    float* __restrict__ out,
    int E, int N)
{
    int gwarp = (blockIdx.x * blockDim.x + threadIdx.x) >> 5;
    int lane  = threadIdx.x & 31;
    if (gwarp >= E) return;

    int s = edge_index[gwarp];
    int d = edge_index[E + gwarp];
    s = min(max(s, 0), N - 1);
    d = min(max(d, 0), N - 1);

    const float4* a = (const float4*)(H + (long long)s * DD);
    const float4* b = (const float4*)(H + (long long)d * DD);
    float4 av = a[lane];
    float4 bv = b[lane];
    float sum = av.x * bv.x + av.y * bv.y + av.z * bv.z + av.w * bv.w;

#pragma unroll
    for (int o = 16; o > 0; o >>= 1)
        sum += __shfl_xor_sync(0xFFFFFFFFu, sum, o);

    if (lane == 0) out[gwarp] = sum;
}

__global__ void label_copy_kernel(const int* __restrict__ lbl,
                                  float* __restrict__ out, int E)
{
    int i = blockIdx.x * blockDim.x + threadIdx.x;
    if (i < E) out[i] = (float)lbl[i];
}

extern "C" void kernel_launch(void* const* d_in, const int* in_sizes, int n_in,
                              void* d_out, int out_size)
{
    const float* x   = (const float*)d_in[0];
    const int*   ei  = (const int*)d_in[1];
    const int*   lbl = (const int*)d_in[2];
    const float* W1  = (const float*)d_in[3];
    const float* b1  = (const float*)d_in[4];
    const float* W2  = (const float*)d_in[5];
    const float* b2  = (const float*)d_in[6];

    int N = in_sizes[0] / DD;   // 100000
    int E = in_sizes[2];        // 500000

    float *h1, *h2;
    __nv_bfloat16 *w1hi, *w1lo, *w2hi, *w2lo;
    cudaGetSymbolAddress((void**)&h1, g_h1);
    cudaGetSymbolAddress((void**)&h2, g_h2);
    cudaGetSymbolAddress((void**)&w1hi, g_w1hi);
    cudaGetSymbolAddress((void**)&w1lo, g_w1lo);
    cudaGetSymbolAddress((void**)&w2hi, g_w2hi);
    cudaGetSymbolAddress((void**)&w2lo, g_w2lo);

    cudaFuncSetAttribute(mlp_mma_kernel,
                         cudaFuncAttributeMaxDynamicSharedMemorySize, SMEM_TOTAL);

    wprep_kernel<<<(DD * DD + 255) / 256, 256>>>(W1, w1hi, w1lo);
    wprep_kernel<<<(DD * DD + 255) / 256, 256>>>(W2, w2hi, w2lo);

    int tiles = (N + TILE_M - 1) / TILE_M;
    mlp_mma_kernel<<<tiles, 256, SMEM_TOTAL>>>(x,  w1hi, w1lo, b1, h1, N);
    mlp_mma_kernel<<<tiles, 256, SMEM_TOTAL>>>(h1, w2hi, w2lo, b2, h2, N);

    float* out = (float*)d_out;
    int dot_blocks = (E + 7) / 8;
    edge_dot_kernel<<<dot_blocks, 256>>>(h2, ei, out, E, N);

    if (out_size >= 2 * E) {
        int lb = (E + 255) / 256;
        label_copy_kernel<<<lb, 256>>>(lbl, out + E, E);
    }
}

// round 5
// speedup vs baseline: 1.5453x; 1.0297x over previous
#include <cuda_runtime.h>
#include <cuda_bf16.h>
#include <cstdint>

// ---------------------------------------------------------------------------
// GNNTransductiveEdgeHead via mma.sync (HMMA) split-bf16:
//   X@W ~= Xhi@Whi + Xlo@Whi + Xhi@Wlo  (fp32 accum, residual ~4e-6)
// R5: warp tile 64x32 (was 16x128) -> ldmatrix per warp 216 -> 96.
// Inputs: 0:x f32[N,128] 1:edge_index i32[2,E] 2:edge_label i32[E]
//         3:W1 f32[128,128] 4:b1 f32[128] 5:W2 f32[128,128] 6:b2 f32[128]
// ---------------------------------------------------------------------------

#define DD 128
#define TILE_M 128
#define MAX_NODES 100000

#define S_ROW   272   // 136 bf16 padded row (conflict-free ldmatrix)
#define A_HI_OFF 0
#define A_LO_OFF 34816
#define B_HI_OFF 69632
#define B_LO_OFF 104448
#define BIAS_OFF 139264
#define SMEM_TOTAL (BIAS_OFF + 512)

__device__ float g_h1[MAX_NODES * DD];
__device__ float g_h2[MAX_NODES * DD];
__device__ __nv_bfloat16 g_w1hi[DD * DD];
__device__ __nv_bfloat16 g_w1lo[DD * DD];
__device__ __nv_bfloat16 g_w2hi[DD * DD];
__device__ __nv_bfloat16 g_w2lo[DD * DD];

__device__ __forceinline__ uint32_t smem_u32(const void* p) {
    uint32_t a;
    asm("{ .reg .u64 t; cvta.to.shared.u64 t, %1; cvt.u32.u64 %0, t; }"
        : "=r"(a) : "l"(p));
    return a;
}
__device__ __forceinline__ void ldmatrix_x4(uint32_t& r0, uint32_t& r1,
                                            uint32_t& r2, uint32_t& r3,
                                            uint32_t addr) {
    asm volatile("ldmatrix.sync.aligned.m8n8.x4.shared.b16 {%0,%1,%2,%3}, [%4];"
                 : "=r"(r0), "=r"(r1), "=r"(r2), "=r"(r3) : "r"(addr));
}
__device__ __forceinline__ void ldmatrix_x4_trans(uint32_t& r0, uint32_t& r1,
                                                  uint32_t& r2, uint32_t& r3,
                                                  uint32_t addr) {
    asm volatile("ldmatrix.sync.aligned.m8n8.x4.trans.shared.b16 {%0,%1,%2,%3}, [%4];"
                 : "=r"(r0), "=r"(r1), "=r"(r2), "=r"(r3) : "r"(addr));
}
__device__ __forceinline__ void mma_bf16(float* c, const uint32_t* a,
                                         uint32_t b0, uint32_t b1) {
    asm volatile(
        "mma.sync.aligned.m16n8k16.row.col.f32.bf16.bf16.f32 "
        "{%0,%1,%2,%3}, {%4,%5,%6,%7}, {%8,%9}, {%0,%1,%2,%3};"
        : "+f"(c[0]), "+f"(c[1]), "+f"(c[2]), "+f"(c[3])
        : "r"(a[0]), "r"(a[1]), "r"(a[2]), "r"(a[3]), "r"(b0), "r"(b1));
}

__global__ void wprep_kernel(const float* __restrict__ W,
                             __nv_bfloat16* __restrict__ hi,
                             __nv_bfloat16* __restrict__ lo) {
    int i = blockIdx.x * blockDim.x + threadIdx.x;
    if (i >= DD * DD) return;
    float w = W[i];
    __nv_bfloat16 h = __float2bfloat16_rn(w);
    hi[i] = h;
    lo[i] = __float2bfloat16_rn(w - __bfloat162float(h));
}

// ---------------------------------------------------------------------------
// Fused layer: H[N,128] = relu(X[N,128] @ W + b).
// 256 thr / 8 warps; warp (mg = w&1, ng = w>>1) owns rows [64mg,64mg+64) x
// cols [32ng, 32ng+32).
// ---------------------------------------------------------------------------
__global__ void __launch_bounds__(256) mlp_mma_kernel(
    const float* __restrict__ X,
    const __nv_bfloat16* __restrict__ Whi,
    const __nv_bfloat16* __restrict__ Wlo,
    const float* __restrict__ bias,
    float* __restrict__ H,
    int N)
{
    extern __shared__ __align__(16) char smem[];
    const uint32_t sb = smem_u32(smem);

    const int tid  = threadIdx.x;
    const int warp = tid >> 5;
    const int lane = tid & 31;
    const int row0 = blockIdx.x * TILE_M;

    if (tid < DD) ((float*)(smem + BIAS_OFF))[tid] = bias[tid];

    // --- Stage X: split into hi/lo bf16 tiles ---
    {
        const int row  = tid >> 1;
        const int half = (tid & 1) * 64;
        const int grow = row0 + row;
        const bool ok = grow < N;
        const float4* src = (const float4*)(X + (long long)grow * DD + half);
        char* dhi = smem + A_HI_OFF + row * S_ROW + half * 2;
        char* dlo = smem + A_LO_OFF + row * S_ROW + half * 2;
#pragma unroll
        for (int c0 = 0; c0 < 64; c0 += 8) {
            float4 a, b;
            if (ok) { a = src[c0 >> 2]; b = src[(c0 >> 2) + 1]; }
            else    { a = make_float4(0, 0, 0, 0); b = a; }
            const float v[8] = {a.x, a.y, a.z, a.w, b.x, b.y, b.z, b.w};
            uint32_t hi4[4], lo4[4];
#pragma unroll
            for (int p = 0; p < 4; p++) {
                __nv_bfloat162 h, l;
                h.x = __float2bfloat16_rn(v[2 * p]);
                h.y = __float2bfloat16_rn(v[2 * p + 1]);
                l.x = __float2bfloat16_rn(v[2 * p]     - __bfloat162float(h.x));
                l.y = __float2bfloat16_rn(v[2 * p + 1] - __bfloat162float(h.y));
                hi4[p] = *(uint32_t*)&h;
                lo4[p] = *(uint32_t*)&l;
            }
            *(uint4*)(dhi + c0 * 2) = make_uint4(hi4[0], hi4[1], hi4[2], hi4[3]);
            *(uint4*)(dlo + c0 * 2) = make_uint4(lo4[0], lo4[1], lo4[2], lo4[3]);
        }
    }
    // --- Stage W hi/lo ([k][n] padded rows) ---
    {
        const int row  = tid >> 1;
        const int half = (tid & 1) * 64;
        const uint4* sh = (const uint4*)(Whi + row * DD + half);
        const uint4* sl = (const uint4*)(Wlo + row * DD + half);
        uint4* dh = (uint4*)(smem + B_HI_OFF + row * S_ROW + half * 2);
        uint4* dl = (uint4*)(smem + B_LO_OFF + row * S_ROW + half * 2);
#pragma unroll
        for (int q = 0; q < 8; q++) { dh[q] = sh[q]; dl[q] = sl[q]; }
    }
    __syncthreads();

    // --- Main loop: 8 ksteps; per kstep 12 ldmatrix + 48 mma ---
    const int mg = warp & 1;          // row group (64 rows)
    const int ng = warp >> 1;         // col group (32 cols)

    float acc[4][4][4];               // [mt][nt][frag]
#pragma unroll
    for (int mt = 0; mt < 4; mt++)
#pragma unroll
        for (int nt = 0; nt < 4; nt++)
#pragma unroll
            for (int c = 0; c < 4; c++) acc[mt][nt][c] = 0.f;

    // A lane addressing: row = mg*64 + mt*16 + (lane&15); +16B for k-half
    const uint32_t a_lane = (uint32_t)((mg * 64 + (lane & 15)) * S_ROW +
                                       (lane >> 4) * 16);
    // B lane addressing (trans): k row = ks*16 + (lane&15); col byte = ng*64
    const uint32_t b_lane = (uint32_t)((lane & 15) * S_ROW + ng * 64 +
                                       (lane >> 4) * 16);

#pragma unroll
    for (int ks = 0; ks < 8; ks++) {
        const uint32_t a_k = a_lane + ks * 32;          // k byte offset
        const uint32_t b_k = b_lane + ks * (16 * S_ROW);

        uint32_t ah[4][4], al[4][4];
#pragma unroll
        for (int mt = 0; mt < 4; mt++) {
            const uint32_t off = a_k + mt * (16 * S_ROW);
            ldmatrix_x4(ah[mt][0], ah[mt][1], ah[mt][2], ah[mt][3],
                        sb + A_HI_OFF + off);
            ldmatrix_x4(al[mt][0], al[mt][1], al[mt][2], al[mt][3],
                        sb + A_LO_OFF + off);
        }
        uint32_t bh[4][2], bl[4][2];   // [nt][2]
#pragma unroll
        for (int hf = 0; hf < 2; hf++) {
            uint32_t r0, r1, r2, r3;
            ldmatrix_x4_trans(r0, r1, r2, r3, sb + B_HI_OFF + b_k + hf * 32);
            bh[2 * hf][0] = r0; bh[2 * hf][1] = r1;
            bh[2 * hf + 1][0] = r2; bh[2 * hf + 1][1] = r3;
            ldmatrix_x4_trans(r0, r1, r2, r3, sb + B_LO_OFF + b_k + hf * 32);
            bl[2 * hf][0] = r0; bl[2 * hf][1] = r1;
            bl[2 * hf + 1][0] = r2; bl[2 * hf + 1][1] = r3;
        }

#pragma unroll
        for (int mt = 0; mt < 4; mt++)
#pragma unroll
            for (int nt = 0; nt < 4; nt++) {
                mma_bf16(acc[mt][nt], ah[mt], bh[nt][0], bh[nt][1]);
                mma_bf16(acc[mt][nt], al[mt], bh[nt][0], bh[nt][1]);
                mma_bf16(acc[mt][nt], ah[mt], bl[nt][0], bl[nt][1]);
            }
    }

    // --- Epilogue: bias + relu + store ---
    {
        const float* sBias = (const float*)(smem + BIAS_OFF);
#pragma unroll
        for (int mt = 0; mt < 4; mt++) {
            const int r0 = row0 + mg * 64 + mt * 16 + (lane >> 2);
            const int r1 = r0 + 8;
            float* p0 = H + (long long)r0 * DD;
            float* p1 = H + (long long)r1 * DD;
            const bool ok0 = r0 < N, ok1 = r1 < N;
#pragma unroll
            for (int nt = 0; nt < 4; nt++) {
                const int col = ng * 32 + nt * 8 + (lane & 3) * 2;
                const float bx = sBias[col], by = sBias[col + 1];
                if (ok0) {
                    float2 v;
                    v.x = fmaxf(acc[mt][nt][0] + bx, 0.f);
                    v.y = fmaxf(acc[mt][nt][1] + by, 0.f);
                    *(float2*)(p0 + col) = v;
                }
                if (ok1) {
                    float2 v;
                    v.x = fmaxf(acc[mt][nt][2] + bx, 0.f);
                    v.y = fmaxf(acc[mt][nt][3] + by, 0.f);
                    *(float2*)(p1 + col) = v;
                }
            }
        }
    }
}

// ---------------------------------------------------------------------------
// Edge decode: one warp per edge, 128 dims = 32 lanes x float4, butterfly sum.
// ---------------------------------------------------------------------------
__global__ void __launch_bounds__(256) edge_dot_kernel(
    const float* __restrict__ H,
    const int* __restrict__ edge_index,
    float* __restrict__ out,
    int E, int N)
{
    int gwarp = (blockIdx.x * blockDim.x + threadIdx.x) >> 5;
    int lane  = threadIdx.x & 31;
    if (gwarp >= E) return;

    int s = edge_index[gwarp];
    int d = edge_index[E + gwarp];
    s = min(max(s, 0), N - 1);
    d = min(max(d, 0), N - 1);

    const float4* a = (const float4*)(H + (long long)s * DD);
    const float4* b = (const float4*)(H + (long long)d * DD);
    float4 av = a[lane];
    float4 bv = b[lane];
    float sum = av.x * bv.x + av.y * bv.y + av.z * bv.z + av.w * bv.w;

#pragma unroll
    for (int o = 16; o > 0; o >>= 1)
        sum += __shfl_xor_sync(0xFFFFFFFFu, sum, o);

    if (lane == 0) out[gwarp] = sum;
}

__global__ void label_copy_kernel(const int* __restrict__ lbl,
                                  float* __restrict__ out, int E)
{
    int i = blockIdx.x * blockDim.x + threadIdx.x;
    if (i < E) out[i] = (float)lbl[i];
}

extern "C" void kernel_launch(void* const* d_in, const int* in_sizes, int n_in,
                              void* d_out, int out_size)
{
    const float* x   = (const float*)d_in[0];
    const int*   ei  = (const int*)d_in[1];
    const int*   lbl = (const int*)d_in[2];
    const float* W1  = (const float*)d_in[3];
    const float* b1  = (const float*)d_in[4];
    const float* W2  = (const float*)d_in[5];
    const float* b2  = (const float*)d_in[6];

    int N = in_sizes[0] / DD;   // 100000
    int E = in_sizes[2];        // 500000

    float *h1, *h2;
    __nv_bfloat16 *w1hi, *w1lo, *w2hi, *w2lo;
    cudaGetSymbolAddress((void**)&h1, g_h1);
    cudaGetSymbolAddress((void**)&h2, g_h2);
    cudaGetSymbolAddress((void**)&w1hi, g_w1hi);
    cudaGetSymbolAddress((void**)&w1lo, g_w1lo);
    cudaGetSymbolAddress((void**)&w2hi, g_w2hi);
    cudaGetSymbolAddress((void**)&w2lo, g_w2lo);

    cudaFuncSetAttribute(mlp_mma_kernel,
                         cudaFuncAttributeMaxDynamicSharedMemorySize, SMEM_TOTAL);

    wprep_kernel<<<(DD * DD + 255) / 256, 256>>>(W1, w1hi, w1lo);
    wprep_kernel<<<(DD * DD + 255) / 256, 256>>>(W2, w2hi, w2lo);

    int tiles = (N + TILE_M - 1) / TILE_M;
    mlp_mma_kernel<<<tiles, 256, SMEM_TOTAL>>>(x,  w1hi, w1lo, b1, h1, N);
    mlp_mma_kernel<<<tiles, 256, SMEM_TOTAL>>>(h1, w2hi, w2lo, b2, h2, N);

    float* out = (float*)d_out;
    int dot_blocks = (E + 7) / 8;
    edge_dot_kernel<<<dot_blocks, 256>>>(h2, ei, out, E, N);

    if (out_size >= 2 * E) {
        int lb = (E + 255) / 256;
        label_copy_kernel<<<lb, 256>>>(lbl, out + E, E);
    }
}

// round 6
// speedup vs baseline: 1.9780x; 1.2801x over previous
#include <cuda_runtime.h>
#include <cuda_bf16.h>
#include <cstdint>

// ---------------------------------------------------------------------------
// GNNTransductiveEdgeHead, R6: persistent fused 2-layer MLP on mma.sync.
//   h2 = relu(relu(x@W1+b1)@W2+b2);  pred[e] = dot(h2[src], h2[dst])
// Split-bf16 3-term GEMM (fp32-class accuracy): X@W ~= Xhi@Whi+Xlo@Whi+Xhi@Wlo
// Persistent CTAs keep W1/W2 (hi/lo) in SMEM; h1 never leaves SMEM; next
// tile's X is prefetched into registers during MMA.
// ---------------------------------------------------------------------------

#define DD 128
#define TILE_M 128
#define MAX_NODES 100000
#define NSM 148

#define S_ROW 272           // 136 bf16 padded row (conflict-free ldmatrix)
#define W1H_OFF 0
#define W1L_OFF 34816
#define W2H_OFF 69632
#define W2L_OFF 104448
#define AH_OFF  139264
#define AL_OFF  174080
#define B1_OFF  208896
#define B2_OFF  209408
#define SMEM_TOTAL 209920

__device__ float g_h2[MAX_NODES * DD];
__device__ __nv_bfloat16 g_w1hi[DD * DD];
__device__ __nv_bfloat16 g_w1lo[DD * DD];
__device__ __nv_bfloat16 g_w2hi[DD * DD];
__device__ __nv_bfloat16 g_w2lo[DD * DD];

__device__ __forceinline__ uint32_t smem_u32(const void* p) {
    uint32_t a;
    asm("{ .reg .u64 t; cvta.to.shared.u64 t, %1; cvt.u32.u64 %0, t; }"
        : "=r"(a) : "l"(p));
    return a;
}
__device__ __forceinline__ void ldmatrix_x4(uint32_t& r0, uint32_t& r1,
                                            uint32_t& r2, uint32_t& r3,
                                            uint32_t addr) {
    asm volatile("ldmatrix.sync.aligned.m8n8.x4.shared.b16 {%0,%1,%2,%3}, [%4];"
                 : "=r"(r0), "=r"(r1), "=r"(r2), "=r"(r3) : "r"(addr));
}
__device__ __forceinline__ void ldmatrix_x4_trans(uint32_t& r0, uint32_t& r1,
                                                  uint32_t& r2, uint32_t& r3,
                                                  uint32_t addr) {
    asm volatile("ldmatrix.sync.aligned.m8n8.x4.trans.shared.b16 {%0,%1,%2,%3}, [%4];"
                 : "=r"(r0), "=r"(r1), "=r"(r2), "=r"(r3) : "r"(addr));
}
__device__ __forceinline__ void mma_bf16(float* c, const uint32_t* a,
                                         uint32_t b0, uint32_t b1) {
    asm volatile(
        "mma.sync.aligned.m16n8k16.row.col.f32.bf16.bf16.f32 "
        "{%0,%1,%2,%3}, {%4,%5,%6,%7}, {%8,%9}, {%0,%1,%2,%3};"
        : "+f"(c[0]), "+f"(c[1]), "+f"(c[2]), "+f"(c[3])
        : "r"(a[0]), "r"(a[1]), "r"(a[2]), "r"(a[3]), "r"(b0), "r"(b1));
}
__device__ __forceinline__ void split2(float x, float y,
                                       uint32_t& hi, uint32_t& lo) {
    __nv_bfloat162 h, l;
    h.x = __float2bfloat16_rn(x);
    h.y = __float2bfloat16_rn(y);
    l.x = __float2bfloat16_rn(x - __bfloat162float(h.x));
    l.y = __float2bfloat16_rn(y - __bfloat162float(h.y));
    hi = *(uint32_t*)&h;
    lo = *(uint32_t*)&l;
}

__global__ void wprep_kernel(const float* __restrict__ W,
                             __nv_bfloat16* __restrict__ hi,
                             __nv_bfloat16* __restrict__ lo) {
    int i = blockIdx.x * blockDim.x + threadIdx.x;
    if (i >= DD * DD) return;
    float w = W[i];
    __nv_bfloat16 h = __float2bfloat16_rn(w);
    hi[i] = h;
    lo[i] = __float2bfloat16_rn(w - __bfloat162float(h));
}

// 3-term split-bf16 MMA over one staged A tile vs one W panel.
// acc[4][4][4] must be zeroed by caller. Addresses are lane-resolved bases.
__device__ __forceinline__ void mma_3term(float acc[4][4][4],
                                          uint32_t aH, uint32_t aL,
                                          uint32_t bH, uint32_t bL) {
#pragma unroll
    for (int ks = 0; ks < 8; ks++) {
        uint32_t ah[4][4], al[4][4];
#pragma unroll
        for (int mt = 0; mt < 4; mt++) {
            const uint32_t off = ks * 32 + mt * (16 * S_ROW);
            ldmatrix_x4(ah[mt][0], ah[mt][1], ah[mt][2], ah[mt][3], aH + off);
            ldmatrix_x4(al[mt][0], al[mt][1], al[mt][2], al[mt][3], aL + off);
        }
        uint32_t bh[4][2], bl[4][2];
#pragma unroll
        for (int hf = 0; hf < 2; hf++) {
            const uint32_t off = ks * (16 * S_ROW) + hf * 32;
            uint32_t r0, r1, r2, r3;
            ldmatrix_x4_trans(r0, r1, r2, r3, bH + off);
            bh[2 * hf][0] = r0; bh[2 * hf][1] = r1;
            bh[2 * hf + 1][0] = r2; bh[2 * hf + 1][1] = r3;
            ldmatrix_x4_trans(r0, r1, r2, r3, bL + off);
            bl[2 * hf][0] = r0; bl[2 * hf][1] = r1;
            bl[2 * hf + 1][0] = r2; bl[2 * hf + 1][1] = r3;
        }
#pragma unroll
        for (int mt = 0; mt < 4; mt++)
#pragma unroll
            for (int nt = 0; nt < 4; nt++) {
                mma_bf16(acc[mt][nt], ah[mt], bh[nt][0], bh[nt][1]);
                mma_bf16(acc[mt][nt], al[mt], bh[nt][0], bh[nt][1]);
                mma_bf16(acc[mt][nt], ah[mt], bl[nt][0], bl[nt][1]);
            }
    }
}

// Convert 16 float4 (one thread's 64 X values) and STS into A hi/lo buffers.
__device__ __forceinline__ void stage_sts(char* smem, const float4* xv, int tid) {
    const int row  = tid >> 1;
    const int half = (tid & 1) * 64;
    char* dh = smem + AH_OFF + row * S_ROW + half * 2;
    char* dl = smem + AL_OFF + row * S_ROW + half * 2;
#pragma unroll
    for (int q = 0; q < 8; q++) {
        const float4 a = xv[2 * q], b = xv[2 * q + 1];
        uint4 hv, lv;
        split2(a.x, a.y, hv.x, lv.x);
        split2(a.z, a.w, hv.y, lv.y);
        split2(b.x, b.y, hv.z, lv.z);
        split2(b.z, b.w, hv.w, lv.w);
        *(uint4*)(dh + q * 16) = hv;
        *(uint4*)(dl + q * 16) = lv;
    }
}
__device__ __forceinline__ void load_x(const float* X, float4* xv,
                                       int row0, int N, int tid) {
    const int row  = tid >> 1;
    const int half = (tid & 1) * 64;
    const int grow = row0 + row;
    const bool ok = grow < N;
    const float4* src = (const float4*)(X + (long long)grow * DD + half);
#pragma unroll
    for (int p = 0; p < 16; p++)
        xv[p] = ok ? src[p] : make_float4(0.f, 0.f, 0.f, 0.f);
}

// ---------------------------------------------------------------------------
// Persistent fused MLP. 256 thr / 8 warps: warp (mg=w&1, ng=w>>1) owns
// rows [64mg,64mg+64) x cols [32ng,32ng+32) of each 128x128 tile.
// ---------------------------------------------------------------------------
__global__ void __launch_bounds__(256) mlp_fused_kernel(
    const float* __restrict__ X,
    const __nv_bfloat16* __restrict__ W1h, const __nv_bfloat16* __restrict__ W1l,
    const __nv_bfloat16* __restrict__ W2h, const __nv_bfloat16* __restrict__ W2l,
    const float* __restrict__ bias1, const float* __restrict__ bias2,
    float* __restrict__ H2,
    int N, int T)
{
    extern __shared__ __align__(16) char smem[];
    const uint32_t sb = smem_u32(smem);
    const int tid  = threadIdx.x;
    const int warp = tid >> 5;
    const int lane = tid & 31;
    const int mg = warp & 1;
    const int ng = warp >> 1;

    // --- Prologue: stage W panels + biases (once per CTA) ---
    {
        const int row  = tid >> 1;
        const int half = (tid & 1) * 64;
        uint4* d1h = (uint4*)(smem + W1H_OFF + row * S_ROW + half * 2);
        uint4* d1l = (uint4*)(smem + W1L_OFF + row * S_ROW + half * 2);
        uint4* d2h = (uint4*)(smem + W2H_OFF + row * S_ROW + half * 2);
        uint4* d2l = (uint4*)(smem + W2L_OFF + row * S_ROW + half * 2);
        const uint4* s1h = (const uint4*)(W1h + row * DD + half);
        const uint4* s1l = (const uint4*)(W1l + row * DD + half);
        const uint4* s2h = (const uint4*)(W2h + row * DD + half);
        const uint4* s2l = (const uint4*)(W2l + row * DD + half);
#pragma unroll
        for (int q = 0; q < 8; q++) {
            d1h[q] = s1h[q]; d1l[q] = s1l[q];
            d2h[q] = s2h[q]; d2l[q] = s2l[q];
        }
    }
    if (tid < DD) {
        ((float*)(smem + B1_OFF))[tid] = bias1[tid];
        ((float*)(smem + B2_OFF))[tid] = bias2[tid];
    }

    // Stage first tile directly.
    int t = blockIdx.x;
    if (t < T) {
        float4 xv[16];
        load_x(X, xv, t * TILE_M, N, tid);
        stage_sts(smem, xv, tid);
    }
    __syncthreads();

    // Lane-resolved base addresses.
    const uint32_t a_off = (uint32_t)((mg * 64 + (lane & 15)) * S_ROW +
                                      (lane >> 4) * 16);
    const uint32_t b_off = (uint32_t)((lane & 15) * S_ROW + ng * 64 +
                                      (lane >> 4) * 16);
    const uint32_t aH  = sb + AH_OFF  + a_off;
    const uint32_t aL  = sb + AL_OFF  + a_off;
    const uint32_t b1H = sb + W1H_OFF + b_off;
    const uint32_t b1L = sb + W1L_OFF + b_off;
    const uint32_t b2H = sb + W2H_OFF + b_off;
    const uint32_t b2L = sb + W2L_OFF + b_off;
    const float* sB1 = (const float*)(smem + B1_OFF);
    const float* sB2 = (const float*)(smem + B2_OFF);

    for (; t < T; t += NSM) {
        const int tn = t + NSM;
        const bool have_next = tn < T;

        // Prefetch next tile's X into registers (latency hidden by MMA).
        float4 xv[16];
        if (have_next) load_x(X, xv, tn * TILE_M, N, tid);

        float acc[4][4][4];
#pragma unroll
        for (int mt = 0; mt < 4; mt++)
#pragma unroll
            for (int nt = 0; nt < 4; nt++)
#pragma unroll
                for (int c = 0; c < 4; c++) acc[mt][nt][c] = 0.f;

        // --- Layer 1 MMAs ---
        mma_3term(acc, aH, aL, b1H, b1L);
        __syncthreads();   // all warps done reading A before overwrite

        // --- Epilogue 1: h1 = relu(acc+b1), split-bf16 back into A buffer ---
#pragma unroll
        for (int mt = 0; mt < 4; mt++) {
            const int r0 = mg * 64 + mt * 16 + (lane >> 2);
            const int r1 = r0 + 8;
#pragma unroll
            for (int nt = 0; nt < 4; nt++) {
                const int c = ng * 32 + nt * 8 + (lane & 3) * 2;
                const float bx = sB1[c], by = sB1[c + 1];
                const float v0 = fmaxf(acc[mt][nt][0] + bx, 0.f);
                const float v1 = fmaxf(acc[mt][nt][1] + by, 0.f);
                const float v2 = fmaxf(acc[mt][nt][2] + bx, 0.f);
                const float v3 = fmaxf(acc[mt][nt][3] + by, 0.f);
                uint32_t hi, lo;
                split2(v0, v1, hi, lo);
                *(uint32_t*)(smem + AH_OFF + r0 * S_ROW + c * 2) = hi;
                *(uint32_t*)(smem + AL_OFF + r0 * S_ROW + c * 2) = lo;
                split2(v2, v3, hi, lo);
                *(uint32_t*)(smem + AH_OFF + r1 * S_ROW + c * 2) = hi;
                *(uint32_t*)(smem + AL_OFF + r1 * S_ROW + c * 2) = lo;
            }
        }
        __syncthreads();   // h1 visible to all warps

        // --- Layer 2 MMAs ---
#pragma unroll
        for (int mt = 0; mt < 4; mt++)
#pragma unroll
            for (int nt = 0; nt < 4; nt++)
#pragma unroll
                for (int c = 0; c < 4; c++) acc[mt][nt][c] = 0.f;
        mma_3term(acc, aH, aL, b2H, b2L);
        __syncthreads();   // all warps done reading A before next-tile STS

        // --- Epilogue 2: h2 = relu(acc+b2) -> global ---
        const int row0 = t * TILE_M;
#pragma unroll
        for (int mt = 0; mt < 4; mt++) {
            const int r0 = row0 + mg * 64 + mt * 16 + (lane >> 2);
            const int r1 = r0 + 8;
            float* p0 = H2 + (long long)r0 * DD;
            float* p1 = H2 + (long long)r1 * DD;
            const bool ok0 = r0 < N, ok1 = r1 < N;
#pragma unroll
            for (int nt = 0; nt < 4; nt++) {
                const int c = ng * 32 + nt * 8 + (lane & 3) * 2;
                const float bx = sB2[c], by = sB2[c + 1];
                if (ok0) {
                    float2 v;
                    v.x = fmaxf(acc[mt][nt][0] + bx, 0.f);
                    v.y = fmaxf(acc[mt][nt][1] + by, 0.f);
                    *(float2*)(p0 + c) = v;
                }
                if (ok1) {
                    float2 v;
                    v.x = fmaxf(acc[mt][nt][2] + bx, 0.f);
                    v.y = fmaxf(acc[mt][nt][3] + by, 0.f);
                    *(float2*)(p1 + c) = v;
                }
            }
        }

        // Stage next tile from prefetched registers.
        if (have_next) stage_sts(smem, xv, tid);
        __syncthreads();
    }
}

// ---------------------------------------------------------------------------
// Edge decode: one warp per edge, 128 dims = 32 lanes x float4, butterfly sum.
// ---------------------------------------------------------------------------
__global__ void __launch_bounds__(256) edge_dot_kernel(
    const float* __restrict__ H,
    const int* __restrict__ edge_index,
    float* __restrict__ out,
    int E, int N)
{
    int gwarp = (blockIdx.x * blockDim.x + threadIdx.x) >> 5;
    int lane  = threadIdx.x & 31;
    if (gwarp >= E) return;

    int s = edge_index[gwarp];
    int d = edge_index[E + gwarp];
    s = min(max(s, 0), N - 1);
    d = min(max(d, 0), N - 1);

    const float4* a = (const float4*)(H + (long long)s * DD);
    const float4* b = (const float4*)(H + (long long)d * DD);
    float4 av = a[lane];
    float4 bv = b[lane];
    float sum = av.x * bv.x + av.y * bv.y + av.z * bv.z + av.w * bv.w;

#pragma unroll
    for (int o = 16; o > 0; o >>= 1)
        sum += __shfl_xor_sync(0xFFFFFFFFu, sum, o);

    if (lane == 0) out[gwarp] = sum;
}

__global__ void label_copy_kernel(const int* __restrict__ lbl,
                                  float* __restrict__ out, int E)
{
    int i = blockIdx.x * blockDim.x + threadIdx.x;
    if (i < E) out[i] = (float)lbl[i];
}

extern "C" void kernel_launch(void* const* d_in, const int* in_sizes, int n_in,
                              void* d_out, int out_size)
{
    const float* x   = (const float*)d_in[0];
    const int*   ei  = (const int*)d_in[1];
    const int*   lbl = (const int*)d_in[2];
    const float* W1  = (const float*)d_in[3];
    const float* b1  = (const float*)d_in[4];
    const float* W2  = (const float*)d_in[5];
    const float* b2  = (const float*)d_in[6];

    int N = in_sizes[0] / DD;   // 100000
    int E = in_sizes[2];        // 500000

    float* h2;
    __nv_bfloat16 *w1hi, *w1lo, *w2hi, *w2lo;
    cudaGetSymbolAddress((void**)&h2, g_h2);
    cudaGetSymbolAddress((void**)&w1hi, g_w1hi);
    cudaGetSymbolAddress((void**)&w1lo, g_w1lo);
    cudaGetSymbolAddress((void**)&w2hi, g_w2hi);
    cudaGetSymbolAddress((void**)&w2lo, g_w2lo);

    cudaFuncSetAttribute(mlp_fused_kernel,
                         cudaFuncAttributeMaxDynamicSharedMemorySize, SMEM_TOTAL);

    wprep_kernel<<<(DD * DD + 255) / 256, 256>>>(W1, w1hi, w1lo);
    wprep_kernel<<<(DD * DD + 255) / 256, 256>>>(W2, w2hi, w2lo);

    int T = (N + TILE_M - 1) / TILE_M;
    mlp_fused_kernel<<<NSM, 256, SMEM_TOTAL>>>(x, w1hi, w1lo, w2hi, w2lo,
                                               b1, b2, h2, N, T);

    float* out = (float*)d_out;
    int dot_blocks = (E + 7) / 8;
    edge_dot_kernel<<<dot_blocks, 256>>>(h2, ei, out, E, N);

    if (out_size >= 2 * E) {
        int lb = (E + 255) / 256;
        label_copy_kernel<<<lb, 256>>>(lbl, out + E, E);
    }
}

// round 7
// speedup vs baseline: 2.1908x; 1.1076x over previous
#include <cuda_runtime.h>
#include <cuda_bf16.h>
#include <cstdint>

// ---------------------------------------------------------------------------
// GNNTransductiveEdgeHead, R7:
//   persistent fused 2-layer split-bf16 MLP (16 warps/CTA) + 2-edge-per-warp
//   gather/dot with fused label output.
// ---------------------------------------------------------------------------

#define DD 128
#define TILE_M 128
#define MAX_NODES 100000
#define NSM 148

#define S_ROW 272           // 136 bf16 padded row (conflict-free ldmatrix)
#define W1H_OFF 0
#define W1L_OFF 34816
#define W2H_OFF 69632
#define W2L_OFF 104448
#define AH_OFF  139264
#define AL_OFF  174080
#define B1_OFF  208896
#define B2_OFF  209408
#define SMEM_TOTAL 209920

__device__ float g_h2[MAX_NODES * DD];
__device__ __nv_bfloat16 g_w1hi[DD * DD];
__device__ __nv_bfloat16 g_w1lo[DD * DD];
__device__ __nv_bfloat16 g_w2hi[DD * DD];
__device__ __nv_bfloat16 g_w2lo[DD * DD];

__device__ __forceinline__ uint32_t smem_u32(const void* p) {
    uint32_t a;
    asm("{ .reg .u64 t; cvta.to.shared.u64 t, %1; cvt.u32.u64 %0, t; }"
        : "=r"(a) : "l"(p));
    return a;
}
__device__ __forceinline__ void ldmatrix_x4(uint32_t& r0, uint32_t& r1,
                                            uint32_t& r2, uint32_t& r3,
                                            uint32_t addr) {
    asm volatile("ldmatrix.sync.aligned.m8n8.x4.shared.b16 {%0,%1,%2,%3}, [%4];"
                 : "=r"(r0), "=r"(r1), "=r"(r2), "=r"(r3) : "r"(addr));
}
__device__ __forceinline__ void ldmatrix_x4_trans(uint32_t& r0, uint32_t& r1,
                                                  uint32_t& r2, uint32_t& r3,
                                                  uint32_t addr) {
    asm volatile("ldmatrix.sync.aligned.m8n8.x4.trans.shared.b16 {%0,%1,%2,%3}, [%4];"
                 : "=r"(r0), "=r"(r1), "=r"(r2), "=r"(r3) : "r"(addr));
}
__device__ __forceinline__ void mma_bf16(float* c, const uint32_t* a,
                                         uint32_t b0, uint32_t b1) {
    asm volatile(
        "mma.sync.aligned.m16n8k16.row.col.f32.bf16.bf16.f32 "
        "{%0,%1,%2,%3}, {%4,%5,%6,%7}, {%8,%9}, {%0,%1,%2,%3};"
        : "+f"(c[0]), "+f"(c[1]), "+f"(c[2]), "+f"(c[3])
        : "r"(a[0]), "r"(a[1]), "r"(a[2]), "r"(a[3]), "r"(b0), "r"(b1));
}
__device__ __forceinline__ void split2(float x, float y,
                                       uint32_t& hi, uint32_t& lo) {
    __nv_bfloat162 h, l;
    h.x = __float2bfloat16_rn(x);
    h.y = __float2bfloat16_rn(y);
    l.x = __float2bfloat16_rn(x - __bfloat162float(h.x));
    l.y = __float2bfloat16_rn(y - __bfloat162float(h.y));
    hi = *(uint32_t*)&h;
    lo = *(uint32_t*)&l;
}

__global__ void wprep_kernel(const float* __restrict__ W,
                             __nv_bfloat16* __restrict__ hi,
                             __nv_bfloat16* __restrict__ lo) {
    int i = blockIdx.x * blockDim.x + threadIdx.x;
    if (i >= DD * DD) return;
    float w = W[i];
    __nv_bfloat16 h = __float2bfloat16_rn(w);
    hi[i] = h;
    lo[i] = __float2bfloat16_rn(w - __bfloat162float(h));
}

// 3-term split-bf16 MMA: warp tile 32(m) x 32(n), K=128.
__device__ __forceinline__ void mma_3term(float acc[2][4][4],
                                          uint32_t aH, uint32_t aL,
                                          uint32_t bH, uint32_t bL) {
#pragma unroll
    for (int ks = 0; ks < 8; ks++) {
        uint32_t ah[2][4], al[2][4];
#pragma unroll
        for (int mt = 0; mt < 2; mt++) {
            const uint32_t off = ks * 32 + mt * (16 * S_ROW);
            ldmatrix_x4(ah[mt][0], ah[mt][1], ah[mt][2], ah[mt][3], aH + off);
            ldmatrix_x4(al[mt][0], al[mt][1], al[mt][2], al[mt][3], aL + off);
        }
        uint32_t bh[4][2], bl[4][2];
#pragma unroll
        for (int hf = 0; hf < 2; hf++) {
            const uint32_t off = ks * (16 * S_ROW) + hf * 32;
            uint32_t r0, r1, r2, r3;
            ldmatrix_x4_trans(r0, r1, r2, r3, bH + off);
            bh[2 * hf][0] = r0; bh[2 * hf][1] = r1;
            bh[2 * hf + 1][0] = r2; bh[2 * hf + 1][1] = r3;
            ldmatrix_x4_trans(r0, r1, r2, r3, bL + off);
            bl[2 * hf][0] = r0; bl[2 * hf][1] = r1;
            bl[2 * hf + 1][0] = r2; bl[2 * hf + 1][1] = r3;
        }
#pragma unroll
        for (int mt = 0; mt < 2; mt++)
#pragma unroll
            for (int nt = 0; nt < 4; nt++) {
                mma_bf16(acc[mt][nt], ah[mt], bh[nt][0], bh[nt][1]);
                mma_bf16(acc[mt][nt], al[mt], bh[nt][0], bh[nt][1]);
                mma_bf16(acc[mt][nt], ah[mt], bl[nt][0], bl[nt][1]);
            }
    }
}

// 512-thread staging: thread owns row tid>>2, col quarter (tid&3)*32.
__device__ __forceinline__ void load_x(const float* X, float4* xv,
                                       int row0, int N, int tid) {
    const int row = tid >> 2;
    const int qc  = (tid & 3) * 32;
    const int grow = row0 + row;
    const bool ok = grow < N;
    const float4* src = (const float4*)(X + (long long)grow * DD + qc);
#pragma unroll
    for (int p = 0; p < 8; p++)
        xv[p] = ok ? src[p] : make_float4(0.f, 0.f, 0.f, 0.f);
}
__device__ __forceinline__ void stage_sts(char* smem, const float4* xv, int tid) {
    const int row = tid >> 2;
    const int qc  = (tid & 3) * 32;
    char* dh = smem + AH_OFF + row * S_ROW + qc * 2;
    char* dl = smem + AL_OFF + row * S_ROW + qc * 2;
#pragma unroll
    for (int q = 0; q < 4; q++) {
        const float4 a = xv[2 * q], b = xv[2 * q + 1];
        uint4 hv, lv;
        split2(a.x, a.y, hv.x, lv.x);
        split2(a.z, a.w, hv.y, lv.y);
        split2(b.x, b.y, hv.z, lv.z);
        split2(b.z, b.w, hv.w, lv.w);
        *(uint4*)(dh + q * 16) = hv;
        *(uint4*)(dl + q * 16) = lv;
    }
}

// ---------------------------------------------------------------------------
// Persistent fused MLP. 512 thr / 16 warps: warp (mg=w&3, ng=w>>2) owns
// rows [32mg,32mg+32) x cols [32ng,32ng+32) of each 128x128 tile.
// ---------------------------------------------------------------------------
__global__ void __launch_bounds__(512) mlp_fused_kernel(
    const float* __restrict__ X,
    const __nv_bfloat16* __restrict__ W1h, const __nv_bfloat16* __restrict__ W1l,
    const __nv_bfloat16* __restrict__ W2h, const __nv_bfloat16* __restrict__ W2l,
    const float* __restrict__ bias1, const float* __restrict__ bias2,
    float* __restrict__ H2,
    int N, int T)
{
    extern __shared__ __align__(16) char smem[];
    const uint32_t sb = smem_u32(smem);
    const int tid  = threadIdx.x;
    const int warp = tid >> 5;
    const int lane = tid & 31;
    const int mg = warp & 3;
    const int ng = warp >> 2;

    // --- Prologue: stage W panels + biases (once per CTA) ---
    {
        const int row = tid >> 2;
        const int qc  = (tid & 3) * 32;
        uint4* d1h = (uint4*)(smem + W1H_OFF + row * S_ROW + qc * 2);
        uint4* d1l = (uint4*)(smem + W1L_OFF + row * S_ROW + qc * 2);
        uint4* d2h = (uint4*)(smem + W2H_OFF + row * S_ROW + qc * 2);
        uint4* d2l = (uint4*)(smem + W2L_OFF + row * S_ROW + qc * 2);
        const uint4* s1h = (const uint4*)(W1h + row * DD + qc);
        const uint4* s1l = (const uint4*)(W1l + row * DD + qc);
        const uint4* s2h = (const uint4*)(W2h + row * DD + qc);
        const uint4* s2l = (const uint4*)(W2l + row * DD + qc);
#pragma unroll
        for (int q = 0; q < 4; q++) {
            d1h[q] = s1h[q]; d1l[q] = s1l[q];
            d2h[q] = s2h[q]; d2l[q] = s2l[q];
        }
    }
    if (tid < DD) {
        ((float*)(smem + B1_OFF))[tid] = bias1[tid];
        ((float*)(smem + B2_OFF))[tid] = bias2[tid];
    }

    int t = blockIdx.x;
    if (t < T) {
        float4 xv[8];
        load_x(X, xv, t * TILE_M, N, tid);
        stage_sts(smem, xv, tid);
    }
    __syncthreads();

    const uint32_t a_off = (uint32_t)((mg * 32 + (lane & 15)) * S_ROW +
                                      (lane >> 4) * 16);
    const uint32_t b_off = (uint32_t)((lane & 15) * S_ROW + ng * 64 +
                                      (lane >> 4) * 16);
    const uint32_t aH  = sb + AH_OFF  + a_off;
    const uint32_t aL  = sb + AL_OFF  + a_off;
    const uint32_t b1H = sb + W1H_OFF + b_off;
    const uint32_t b1L = sb + W1L_OFF + b_off;
    const uint32_t b2H = sb + W2H_OFF + b_off;
    const uint32_t b2L = sb + W2L_OFF + b_off;
    const float* sB1 = (const float*)(smem + B1_OFF);
    const float* sB2 = (const float*)(smem + B2_OFF);

    for (; t < T; t += NSM) {
        const int tn = t + NSM;
        const bool have_next = tn < T;

        float4 xv[8];
        if (have_next) load_x(X, xv, tn * TILE_M, N, tid);

        float acc[2][4][4];
#pragma unroll
        for (int mt = 0; mt < 2; mt++)
#pragma unroll
            for (int nt = 0; nt < 4; nt++)
#pragma unroll
                for (int c = 0; c < 4; c++) acc[mt][nt][c] = 0.f;

        // --- Layer 1 ---
        mma_3term(acc, aH, aL, b1H, b1L);
        __syncthreads();

        // --- Epilogue 1: h1 split-bf16 back into A buffer ---
#pragma unroll
        for (int mt = 0; mt < 2; mt++) {
            const int r0 = mg * 32 + mt * 16 + (lane >> 2);
            const int r1 = r0 + 8;
#pragma unroll
            for (int nt = 0; nt < 4; nt++) {
                const int c = ng * 32 + nt * 8 + (lane & 3) * 2;
                const float bx = sB1[c], by = sB1[c + 1];
                const float v0 = fmaxf(acc[mt][nt][0] + bx, 0.f);
                const float v1 = fmaxf(acc[mt][nt][1] + by, 0.f);
                const float v2 = fmaxf(acc[mt][nt][2] + bx, 0.f);
                const float v3 = fmaxf(acc[mt][nt][3] + by, 0.f);
                uint32_t hi, lo;
                split2(v0, v1, hi, lo);
                *(uint32_t*)(smem + AH_OFF + r0 * S_ROW + c * 2) = hi;
                *(uint32_t*)(smem + AL_OFF + r0 * S_ROW + c * 2) = lo;
                split2(v2, v3, hi, lo);
                *(uint32_t*)(smem + AH_OFF + r1 * S_ROW + c * 2) = hi;
                *(uint32_t*)(smem + AL_OFF + r1 * S_ROW + c * 2) = lo;
            }
        }
        __syncthreads();

        // --- Layer 2 ---
#pragma unroll
        for (int mt = 0; mt < 2; mt++)
#pragma unroll
            for (int nt = 0; nt < 4; nt++)
#pragma unroll
                for (int c = 0; c < 4; c++) acc[mt][nt][c] = 0.f;
        mma_3term(acc, aH, aL, b2H, b2L);
        __syncthreads();

        // --- Epilogue 2: h2 -> global ---
        const int row0 = t * TILE_M;
#pragma unroll
        for (int mt = 0; mt < 2; mt++) {
            const int r0 = row0 + mg * 32 + mt * 16 + (lane >> 2);
            const int r1 = r0 + 8;
            float* p0 = H2 + (long long)r0 * DD;
            float* p1 = H2 + (long long)r1 * DD;
            const bool ok0 = r0 < N, ok1 = r1 < N;
#pragma unroll
            for (int nt = 0; nt < 4; nt++) {
                const int c = ng * 32 + nt * 8 + (lane & 3) * 2;
                const float bx = sB2[c], by = sB2[c + 1];
                if (ok0) {
                    float2 v;
                    v.x = fmaxf(acc[mt][nt][0] + bx, 0.f);
                    v.y = fmaxf(acc[mt][nt][1] + by, 0.f);
                    *(float2*)(p0 + c) = v;
                }
                if (ok1) {
                    float2 v;
                    v.x = fmaxf(acc[mt][nt][2] + bx, 0.f);
                    v.y = fmaxf(acc[mt][nt][3] + by, 0.f);
                    *(float2*)(p1 + c) = v;
                }
            }
        }

        if (have_next) stage_sts(smem, xv, tid);
        __syncthreads();
    }
}

// ---------------------------------------------------------------------------
// Edge decode: 2 edges per warp (4 independent 16B loads/lane), fused labels.
// ---------------------------------------------------------------------------
__global__ void __launch_bounds__(256) edge_dot_kernel(
    const float* __restrict__ H,
    const int* __restrict__ edge_index,
    const int* __restrict__ lbl,
    float* __restrict__ out,
    float* __restrict__ lblout,   // nullptr if not needed
    int E, int N)
{
    const int gwarp = (blockIdx.x * blockDim.x + threadIdx.x) >> 5;
    const int lane  = threadIdx.x & 31;
    const int e0 = gwarp * 2;
    const int e1 = e0 + 1;
    if (e0 >= E) return;
    const bool has1 = e1 < E;

    int s0 = edge_index[e0];
    int d0 = edge_index[E + e0];
    int s1 = edge_index[has1 ? e1 : e0];
    int d1 = edge_index[E + (has1 ? e1 : e0)];
    s0 = min(max(s0, 0), N - 1); d0 = min(max(d0, 0), N - 1);
    s1 = min(max(s1, 0), N - 1); d1 = min(max(d1, 0), N - 1);

    const float4 a0 = ((const float4*)(H + (long long)s0 * DD))[lane];
    const float4 b0 = ((const float4*)(H + (long long)d0 * DD))[lane];
    const float4 a1 = ((const float4*)(H + (long long)s1 * DD))[lane];
    const float4 b1 = ((const float4*)(H + (long long)d1 * DD))[lane];

    float s0v = a0.x * b0.x + a0.y * b0.y + a0.z * b0.z + a0.w * b0.w;
    float s1v = a1.x * b1.x + a1.y * b1.y + a1.z * b1.z + a1.w * b1.w;

#pragma unroll
    for (int o = 16; o > 0; o >>= 1) {
        s0v += __shfl_xor_sync(0xFFFFFFFFu, s0v, o);
        s1v += __shfl_xor_sync(0xFFFFFFFFu, s1v, o);
    }

    if (lane == 0) {
        if (has1) *(float2*)(out + e0) = make_float2(s0v, s1v);
        else      out[e0] = s0v;
    }
    if (lblout && lane == 1) {
        lblout[e0] = (float)lbl[e0];
        if (has1) lblout[e1] = (float)lbl[e1];
    }
}

extern "C" void kernel_launch(void* const* d_in, const int* in_sizes, int n_in,
                              void* d_out, int out_size)
{
    const float* x   = (const float*)d_in[0];
    const int*   ei  = (const int*)d_in[1];
    const int*   lbl = (const int*)d_in[2];
    const float* W1  = (const float*)d_in[3];
    const float* b1  = (const float*)d_in[4];
    const float* W2  = (const float*)d_in[5];
    const float* b2  = (const float*)d_in[6];

    int N = in_sizes[0] / DD;   // 100000
    int E = in_sizes[2];        // 500000

    float* h2;
    __nv_bfloat16 *w1hi, *w1lo, *w2hi, *w2lo;
    cudaGetSymbolAddress((void**)&h2, g_h2);
    cudaGetSymbolAddress((void**)&w1hi, g_w1hi);
    cudaGetSymbolAddress((void**)&w1lo, g_w1lo);
    cudaGetSymbolAddress((void**)&w2hi, g_w2hi);
    cudaGetSymbolAddress((void**)&w2lo, g_w2lo);

    cudaFuncSetAttribute(mlp_fused_kernel,
                         cudaFuncAttributeMaxDynamicSharedMemorySize, SMEM_TOTAL);

    wprep_kernel<<<(DD * DD + 255) / 256, 256>>>(W1, w1hi, w1lo);
    wprep_kernel<<<(DD * DD + 255) / 256, 256>>>(W2, w2hi, w2lo);

    int T = (N + TILE_M - 1) / TILE_M;
    mlp_fused_kernel<<<NSM, 512, SMEM_TOTAL>>>(x, w1hi, w1lo, w2hi, w2lo,
                                               b1, b2, h2, N, T);

    float* out = (float*)d_out;
    float* lblout = (out_size >= 2 * E) ? out + E : nullptr;
    int pairs = (E + 1) / 2;                    // 2 edges per warp
    int blocks = (pairs + 7) / 8;               // 8 warps per block
    edge_dot_kernel<<<blocks, 256>>>(h2, ei, lbl, out, lblout, E, N);
}

// round 8
// speedup vs baseline: 2.8218x; 1.2880x over previous
#include <cuda_runtime.h>
#include <cuda_fp16.h>
#include <cuda_bf16.h>
#include <cstdint>

// ---------------------------------------------------------------------------
// GNNTransductiveEdgeHead, R8:
//  - MLP: persistent CTA, TWO independent 8-warp streams (named barriers),
//    swizzled 256B rows, split-bf16 3-term mma.sync, h2 stored fp16.
//  - edge dot: fp16 gathers (half bytes), 2 edges/warp, fused labels.
// ---------------------------------------------------------------------------

#define DD 128
#define TILE 64            // rows per stream-tile
#define MAX_NODES 100000
#define NSM 148

// SMEM layout (bytes)
#define P_W1H 0
#define P_W1L 32768
#define P_W2H 65536
#define P_W2L 98304
#define A_BASE 131072      // + g*32768 (hi); lo at +16384
#define B1_OFF 196608
#define B2_OFF 197120
#define SMEM_TOTAL 197632

__device__ uint4 g_h2h[MAX_NODES * 16];          // h2 as fp16, 256B per node
__device__ __nv_bfloat16 g_w1hi[DD * DD];
__device__ __nv_bfloat16 g_w1lo[DD * DD];
__device__ __nv_bfloat16 g_w2hi[DD * DD];
__device__ __nv_bfloat16 g_w2lo[DD * DD];

__device__ __forceinline__ uint32_t smem_u32(const void* p) {
    uint32_t a;
    asm("{ .reg .u64 t; cvta.to.shared.u64 t, %1; cvt.u32.u64 %0, t; }"
        : "=r"(a) : "l"(p));
    return a;
}
__device__ __forceinline__ void ldmatrix_x4(uint32_t& r0, uint32_t& r1,
                                            uint32_t& r2, uint32_t& r3,
                                            uint32_t addr) {
    asm volatile("ldmatrix.sync.aligned.m8n8.x4.shared.b16 {%0,%1,%2,%3}, [%4];"
                 : "=r"(r0), "=r"(r1), "=r"(r2), "=r"(r3) : "r"(addr));
}
__device__ __forceinline__ void ldmatrix_x4_trans(uint32_t& r0, uint32_t& r1,
                                                  uint32_t& r2, uint32_t& r3,
                                                  uint32_t addr) {
    asm volatile("ldmatrix.sync.aligned.m8n8.x4.trans.shared.b16 {%0,%1,%2,%3}, [%4];"
                 : "=r"(r0), "=r"(r1), "=r"(r2), "=r"(r3) : "r"(addr));
}
__device__ __forceinline__ void mma_bf16(float* c, const uint32_t* a,
                                         uint32_t b0, uint32_t b1) {
    asm volatile(
        "mma.sync.aligned.m16n8k16.row.col.f32.bf16.bf16.f32 "
        "{%0,%1,%2,%3}, {%4,%5,%6,%7}, {%8,%9}, {%0,%1,%2,%3};"
        : "+f"(c[0]), "+f"(c[1]), "+f"(c[2]), "+f"(c[3])
        : "r"(a[0]), "r"(a[1]), "r"(a[2]), "r"(a[3]), "r"(b0), "r"(b1));
}
__device__ __forceinline__ void split2(float x, float y,
                                       uint32_t& hi, uint32_t& lo) {
    __nv_bfloat162 h, l;
    h.x = __float2bfloat16_rn(x);
    h.y = __float2bfloat16_rn(y);
    l.x = __float2bfloat16_rn(x - __bfloat162float(h.x));
    l.y = __float2bfloat16_rn(y - __bfloat162float(h.y));
    hi = *(uint32_t*)&h;
    lo = *(uint32_t*)&l;
}
#define GBAR(gid) asm volatile("bar.sync %0, %1;" :: "r"((gid) + 1), "r"(256) : "memory")

__global__ void wprep_kernel(const float* __restrict__ W,
                             __nv_bfloat16* __restrict__ hi,
                             __nv_bfloat16* __restrict__ lo) {
    int i = blockIdx.x * blockDim.x + threadIdx.x;
    if (i >= DD * DD) return;
    float w = W[i];
    __nv_bfloat16 h = __float2bfloat16_rn(w);
    hi[i] = h;
    lo[i] = __float2bfloat16_rn(w - __bfloat162float(h));
}

// ---------------------------------------------------------------------------
// Persistent fused MLP: 512 thr = 2 streams x 8 warps; stream handles 64-row
// tiles; warp (mg=w&1, ng=w>>1) owns rows [32mg,32mg+32) x cols [32ng,+32).
// ---------------------------------------------------------------------------
__global__ void __launch_bounds__(512, 1) mlp_fused_kernel(
    const float* __restrict__ X,
    const __nv_bfloat16* __restrict__ W1h, const __nv_bfloat16* __restrict__ W1l,
    const __nv_bfloat16* __restrict__ W2h, const __nv_bfloat16* __restrict__ W2l,
    const float* __restrict__ bias1, const float* __restrict__ bias2,
    uint4* __restrict__ H2h,
    int N, int T)
{
    extern __shared__ __align__(16) char smem[];
    const uint32_t sb = smem_u32(smem);
    const int tid  = threadIdx.x;
    const int g    = tid >> 8;        // stream 0/1
    const int tg   = tid & 255;       // thread within stream
    const int warp = tg >> 5;
    const int lane = tid & 31;
    const int mg = warp & 1;
    const int ng = warp >> 1;

    // --- Prologue: stage swizzled W panels (all 512 threads) ---
    {
        const __nv_bfloat16* wsrc[4] = {W1h, W1l, W2h, W2l};
        const uint32_t pdst[4] = {P_W1H, P_W1L, P_W2H, P_W2L};
#pragma unroll
        for (int i = 0; i < 16; i++) {
            int idx = tid + i * 512;           // 8192 chunks total
            int panel = idx >> 11;
            int rem   = idx & 2047;
            int row   = rem >> 4;
            int c     = rem & 15;
            uint4 v = ((const uint4*)(wsrc[panel] + row * DD))[c];
            *(uint4*)(smem + pdst[panel] + row * 256 +
                      ((c ^ (row & 7)) << 4)) = v;
        }
    }
    if (tid < DD) {
        ((float*)(smem + B1_OFF))[tid] = bias1[tid];
        ((float*)(smem + B2_OFF))[tid] = bias2[tid];
    }

    const uint32_t AH = A_BASE + g * 32768;
    const uint32_t AL = AH + 16384;

    // Stage first tile of this stream.
    int t = 2 * blockIdx.x + g;
    if (t < T) {
        const int row = tg >> 2, q4 = tg & 3;
        const int grow = t * TILE + row;
        const bool ok = grow < N;
        const float4* src = (const float4*)(X + (long long)grow * DD + q4 * 32);
        char* dh = smem + AH + row * 256;
        char* dl = smem + AL + row * 256;
        const int r7 = row & 7;
#pragma unroll
        for (int q = 0; q < 4; q++) {
            float4 a = ok ? src[2 * q]     : make_float4(0, 0, 0, 0);
            float4 b = ok ? src[2 * q + 1] : make_float4(0, 0, 0, 0);
            uint4 hv, lv;
            split2(a.x, a.y, hv.x, lv.x);
            split2(a.z, a.w, hv.y, lv.y);
            split2(b.x, b.y, hv.z, lv.z);
            split2(b.z, b.w, hv.w, lv.w);
            const uint32_t off = (((4 * q4 + q) ^ r7) << 4);
            *(uint4*)(dh + off) = hv;
            *(uint4*)(dl + off) = lv;
        }
    }
    __syncthreads();   // W panels + first tiles visible

    // Lane-resolved addressing.
    const int hA = lane >> 4;                 // k-half select
    const int x7 = lane & 7;                  // swizzle xor (rows & k share it)
    const uint32_t aRow = (uint32_t)(mg * 32 + (lane & 15));
    const uint32_t aHb = sb + AH + aRow * 256;
    const uint32_t aLb = sb + AL + aRow * 256;
    const uint32_t bRow = (uint32_t)(lane & 15) * 256;
    const uint32_t p1H = sb + P_W1H + bRow, p1L = sb + P_W1L + bRow;
    const uint32_t p2H = sb + P_W2H + bRow, p2L = sb + P_W2L + bRow;
    const float* sB1 = (const float*)(smem + B1_OFF);
    const float* sB2 = (const float*)(smem + B2_OFF);

    for (; t < T; t += 2 * NSM) {
        const int tn = t + 2 * NSM;
        const bool have_next = tn < T;

        float acc[2][4][4];
#pragma unroll
        for (int mt = 0; mt < 2; mt++)
#pragma unroll
            for (int nt = 0; nt < 4; nt++)
#pragma unroll
                for (int c = 0; c < 4; c++) acc[mt][nt][c] = 0.f;

        // ---- Layer 1 MMAs (A = x) ----
#pragma unroll
        for (int ks = 0; ks < 8; ks++) {
            uint32_t ah[2][4], al[2][4];
#pragma unroll
            for (int mt = 0; mt < 2; mt++) {
                const uint32_t off = mt * 4096 + ((((2 * ks + hA) ^ x7)) << 4);
                ldmatrix_x4(ah[mt][0], ah[mt][1], ah[mt][2], ah[mt][3], aHb + off);
                ldmatrix_x4(al[mt][0], al[mt][1], al[mt][2], al[mt][3], aLb + off);
            }
            uint32_t bh[4][2], bl[4][2];
#pragma unroll
            for (int hf = 0; hf < 2; hf++) {
                const uint32_t off = ks * 4096 +
                    ((((4 * ng + 2 * hf + hA) ^ x7)) << 4);
                uint32_t r0, r1, r2, r3;
                ldmatrix_x4_trans(r0, r1, r2, r3, p1H + off);
                bh[2 * hf][0] = r0; bh[2 * hf][1] = r1;
                bh[2 * hf + 1][0] = r2; bh[2 * hf + 1][1] = r3;
                ldmatrix_x4_trans(r0, r1, r2, r3, p1L + off);
                bl[2 * hf][0] = r0; bl[2 * hf][1] = r1;
                bl[2 * hf + 1][0] = r2; bl[2 * hf + 1][1] = r3;
            }
#pragma unroll
            for (int mt = 0; mt < 2; mt++)
#pragma unroll
                for (int nt = 0; nt < 4; nt++) {
                    mma_bf16(acc[mt][nt], ah[mt], bh[nt][0], bh[nt][1]);
                    mma_bf16(acc[mt][nt], al[mt], bh[nt][0], bh[nt][1]);
                    mma_bf16(acc[mt][nt], ah[mt], bl[nt][0], bl[nt][1]);
                }
        }
        GBAR(g);   // stream done reading A

        // ---- Epilogue 1: h1 = relu(acc+b1) split-bf16 -> A buffer ----
#pragma unroll
        for (int mt = 0; mt < 2; mt++) {
            const int r0 = mg * 32 + mt * 16 + (lane >> 2);
            const int r1 = r0 + 8;
#pragma unroll
            for (int nt = 0; nt < 4; nt++) {
                const int cc = ng * 32 + nt * 8 + (lane & 3) * 2;
                const float bx = sB1[cc], by = sB1[cc + 1];
                const float v0 = fmaxf(acc[mt][nt][0] + bx, 0.f);
                const float v1 = fmaxf(acc[mt][nt][1] + by, 0.f);
                const float v2 = fmaxf(acc[mt][nt][2] + bx, 0.f);
                const float v3 = fmaxf(acc[mt][nt][3] + by, 0.f);
                const uint32_t w0 = ((4 * ng + nt) ^ (r0 & 7)) * 16 + 4 * (lane & 3);
                const uint32_t w1 = ((4 * ng + nt) ^ (r1 & 7)) * 16 + 4 * (lane & 3);
                uint32_t hi, lo;
                split2(v0, v1, hi, lo);
                *(uint32_t*)(smem + AH + r0 * 256 + w0) = hi;
                *(uint32_t*)(smem + AL + r0 * 256 + w0) = lo;
                split2(v2, v3, hi, lo);
                *(uint32_t*)(smem + AH + r1 * 256 + w1) = hi;
                *(uint32_t*)(smem + AL + r1 * 256 + w1) = lo;
            }
        }
        GBAR(g);   // h1 visible

        // Prefetch next tile's X (latency hidden under layer-2 MMAs).
        float4 xv[8];
        if (have_next) {
            const int row = tg >> 2, q4 = tg & 3;
            const int grow = tn * TILE + row;
            const bool ok = grow < N;
            const float4* src =
                (const float4*)(X + (long long)grow * DD + q4 * 32);
#pragma unroll
            for (int p = 0; p < 8; p++)
                xv[p] = ok ? src[p] : make_float4(0, 0, 0, 0);
        }

        // ---- Layer 2 MMAs (A = h1) ----
#pragma unroll
        for (int mt = 0; mt < 2; mt++)
#pragma unroll
            for (int nt = 0; nt < 4; nt++)
#pragma unroll
                for (int c = 0; c < 4; c++) acc[mt][nt][c] = 0.f;
#pragma unroll
        for (int ks = 0; ks < 8; ks++) {
            uint32_t ah[2][4], al[2][4];
#pragma unroll
            for (int mt = 0; mt < 2; mt++) {
                const uint32_t off = mt * 4096 + ((((2 * ks + hA) ^ x7)) << 4);
                ldmatrix_x4(ah[mt][0], ah[mt][1], ah[mt][2], ah[mt][3], aHb + off);
                ldmatrix_x4(al[mt][0], al[mt][1], al[mt][2], al[mt][3], aLb + off);
            }
            uint32_t bh[4][2], bl[4][2];
#pragma unroll
            for (int hf = 0; hf < 2; hf++) {
                const uint32_t off = ks * 4096 +
                    ((((4 * ng + 2 * hf + hA) ^ x7)) << 4);
                uint32_t r0, r1, r2, r3;
                ldmatrix_x4_trans(r0, r1, r2, r3, p2H + off);
                bh[2 * hf][0] = r0; bh[2 * hf][1] = r1;
                bh[2 * hf + 1][0] = r2; bh[2 * hf + 1][1] = r3;
                ldmatrix_x4_trans(r0, r1, r2, r3, p2L + off);
                bl[2 * hf][0] = r0; bl[2 * hf][1] = r1;
                bl[2 * hf + 1][0] = r2; bl[2 * hf + 1][1] = r3;
            }
#pragma unroll
            for (int mt = 0; mt < 2; mt++)
#pragma unroll
                for (int nt = 0; nt < 4; nt++) {
                    mma_bf16(acc[mt][nt], ah[mt], bh[nt][0], bh[nt][1]);
                    mma_bf16(acc[mt][nt], al[mt], bh[nt][0], bh[nt][1]);
                    mma_bf16(acc[mt][nt], ah[mt], bl[nt][0], bl[nt][1]);
                }
        }
        GBAR(g);   // stream done reading A (h1)

        // ---- Epilogue 2: h2 = relu(acc+b2) -> global fp16 ----
        {
            __half* H = (__half*)H2h;
            const int rowb = t * TILE + mg * 32;
#pragma unroll
            for (int mt = 0; mt < 2; mt++) {
                const int r0 = rowb + mt * 16 + (lane >> 2);
                const int r1 = r0 + 8;
                const bool ok0 = r0 < N, ok1 = r1 < N;
#pragma unroll
                for (int nt = 0; nt < 4; nt++) {
                    const int cc = ng * 32 + nt * 8 + (lane & 3) * 2;
                    const float bx = sB2[cc], by = sB2[cc + 1];
                    if (ok0) {
                        __half2 v = __floats2half2_rn(
                            fmaxf(acc[mt][nt][0] + bx, 0.f),
                            fmaxf(acc[mt][nt][1] + by, 0.f));
                        *(__half2*)(H + (long long)r0 * DD + cc) = v;
                    }
                    if (ok1) {
                        __half2 v = __floats2half2_rn(
                            fmaxf(acc[mt][nt][2] + bx, 0.f),
                            fmaxf(acc[mt][nt][3] + by, 0.f));
                        *(__half2*)(H + (long long)r1 * DD + cc) = v;
                    }
                }
            }
        }

        // Stage next tile from prefetched registers.
        if (have_next) {
            const int row = tg >> 2, q4 = tg & 3;
            char* dh = smem + AH + row * 256;
            char* dl = smem + AL + row * 256;
            const int r7 = row & 7;
#pragma unroll
            for (int q = 0; q < 4; q++) {
                uint4 hv, lv;
                split2(xv[2 * q].x, xv[2 * q].y, hv.x, lv.x);
                split2(xv[2 * q].z, xv[2 * q].w, hv.y, lv.y);
                split2(xv[2 * q + 1].x, xv[2 * q + 1].y, hv.z, lv.z);
                split2(xv[2 * q + 1].z, xv[2 * q + 1].w, hv.w, lv.w);
                const uint32_t off = (((4 * q4 + q) ^ r7) << 4);
                *(uint4*)(dh + off) = hv;
                *(uint4*)(dl + off) = lv;
            }
        }
        GBAR(g);
    }
}

// ---------------------------------------------------------------------------
// Edge decode on fp16 h2: 2 edges/warp, 4 halves (8B) per lane per node.
// ---------------------------------------------------------------------------
__global__ void __launch_bounds__(256) edge_dot_kernel(
    const uint4* __restrict__ H16,
    const int* __restrict__ edge_index,
    const int* __restrict__ lbl,
    float* __restrict__ out,
    float* __restrict__ lblout,
    int E, int N)
{
    const int gwarp = (blockIdx.x * blockDim.x + threadIdx.x) >> 5;
    const int lane  = threadIdx.x & 31;
    const int e0 = gwarp * 2;
    const int e1 = e0 + 1;
    if (e0 >= E) return;
    const bool has1 = e1 < E;

    int s0 = edge_index[e0];
    int d0 = edge_index[E + e0];
    int s1 = edge_index[has1 ? e1 : e0];
    int d1 = edge_index[E + (has1 ? e1 : e0)];
    s0 = min(max(s0, 0), N - 1); d0 = min(max(d0, 0), N - 1);
    s1 = min(max(s1, 0), N - 1); d1 = min(max(d1, 0), N - 1);

    const uint2* H = (const uint2*)H16;     // 4 halves per uint2
    const uint2 a0 = H[(long long)s0 * 32 + lane];
    const uint2 b0 = H[(long long)d0 * 32 + lane];
    const uint2 a1 = H[(long long)s1 * 32 + lane];
    const uint2 b1 = H[(long long)d1 * 32 + lane];

    float s0v, s1v;
    {
        float2 ax = __half22float2(*(const __half2*)&a0.x);
        float2 ay = __half22float2(*(const __half2*)&a0.y);
        float2 bx = __half22float2(*(const __half2*)&b0.x);
        float2 by = __half22float2(*(const __half2*)&b0.y);
        s0v = ax.x * bx.x + ax.y * bx.y + ay.x * by.x + ay.y * by.y;
    }
    {
        float2 ax = __half22float2(*(const __half2*)&a1.x);
        float2 ay = __half22float2(*(const __half2*)&a1.y);
        float2 bx = __half22float2(*(const __half2*)&b1.x);
        float2 by = __half22float2(*(const __half2*)&b1.y);
        s1v = ax.x * bx.x + ax.y * bx.y + ay.x * by.x + ay.y * by.y;
    }

#pragma unroll
    for (int o = 16; o > 0; o >>= 1) {
        s0v += __shfl_xor_sync(0xFFFFFFFFu, s0v, o);
        s1v += __shfl_xor_sync(0xFFFFFFFFu, s1v, o);
    }

    if (lane == 0) {
        if (has1) *(float2*)(out + e0) = make_float2(s0v, s1v);
        else      out[e0] = s0v;
    }
    if (lblout && lane == 1) {
        lblout[e0] = (float)lbl[e0];
        if (has1) lblout[e1] = (float)lbl[e1];
    }
}

extern "C" void kernel_launch(void* const* d_in, const int* in_sizes, int n_in,
                              void* d_out, int out_size)
{
    const float* x   = (const float*)d_in[0];
    const int*   ei  = (const int*)d_in[1];
    const int*   lbl = (const int*)d_in[2];
    const float* W1  = (const float*)d_in[3];
    const float* b1  = (const float*)d_in[4];
    const float* W2  = (const float*)d_in[5];
    const float* b2  = (const float*)d_in[6];

    int N = in_sizes[0] / DD;   // 100000
    int E = in_sizes[2];        // 500000

    uint4* h2h;
    __nv_bfloat16 *w1hi, *w1lo, *w2hi, *w2lo;
    cudaGetSymbolAddress((void**)&h2h, g_h2h);
    cudaGetSymbolAddress((void**)&w1hi, g_w1hi);
    cudaGetSymbolAddress((void**)&w1lo, g_w1lo);
    cudaGetSymbolAddress((void**)&w2hi, g_w2hi);
    cudaGetSymbolAddress((void**)&w2lo, g_w2lo);

    cudaFuncSetAttribute(mlp_fused_kernel,
                         cudaFuncAttributeMaxDynamicSharedMemorySize, SMEM_TOTAL);

    wprep_kernel<<<(DD * DD + 255) / 256, 256>>>(W1, w1hi, w1lo);
    wprep_kernel<<<(DD * DD + 255) / 256, 256>>>(W2, w2hi, w2lo);

    int T = (N + TILE - 1) / TILE;
    mlp_fused_kernel<<<NSM, 512, SMEM_TOTAL>>>(x, w1hi, w1lo, w2hi, w2lo,
                                               b1, b2, h2h, N, T);

    float* out = (float*)d_out;
    float* lblout = (out_size >= 2 * E) ? out + E : nullptr;
    int pairs = (E + 1) / 2;
    int blocks = (pairs + 7) / 8;
    edge_dot_kernel<<<blocks, 256>>>(h2h, ei, lbl, out, lblout, E, N);
}

// round 9
// speedup vs baseline: 3.2208x; 1.1414x over previous
#include <cuda_runtime.h>
#include <cuda_fp16.h>
#include <cuda_bf16.h>
#include <cstdint>

// ---------------------------------------------------------------------------
// GNNTransductiveEdgeHead, R9:
//  - MLP: persistent CTA, two 8-warp streams (named barriers), swizzled 256B
//    rows, split-bf16 3-term mma.sync, h2 stored fp16. (unchanged from R8)
//  - edge dot: 16 lanes/edge, 4 edges/warp (issue-bound fix).
// ---------------------------------------------------------------------------

#define DD 128
#define TILE 64            // rows per stream-tile
#define MAX_NODES 100000
#define NSM 148

// SMEM layout (bytes)
#define P_W1H 0
#define P_W1L 32768
#define P_W2H 65536
#define P_W2L 98304
#define A_BASE 131072      // + g*32768 (hi); lo at +16384
#define B1_OFF 196608
#define B2_OFF 197120
#define SMEM_TOTAL 197632

__device__ uint4 g_h2h[MAX_NODES * 16];          // h2 as fp16, 256B per node
__device__ __nv_bfloat16 g_w1hi[DD * DD];
__device__ __nv_bfloat16 g_w1lo[DD * DD];
__device__ __nv_bfloat16 g_w2hi[DD * DD];
__device__ __nv_bfloat16 g_w2lo[DD * DD];

__device__ __forceinline__ uint32_t smem_u32(const void* p) {
    uint32_t a;
    asm("{ .reg .u64 t; cvta.to.shared.u64 t, %1; cvt.u32.u64 %0, t; }"
        : "=r"(a) : "l"(p));
    return a;
}
__device__ __forceinline__ void ldmatrix_x4(uint32_t& r0, uint32_t& r1,
                                            uint32_t& r2, uint32_t& r3,
                                            uint32_t addr) {
    asm volatile("ldmatrix.sync.aligned.m8n8.x4.shared.b16 {%0,%1,%2,%3}, [%4];"
                 : "=r"(r0), "=r"(r1), "=r"(r2), "=r"(r3) : "r"(addr));
}
__device__ __forceinline__ void ldmatrix_x4_trans(uint32_t& r0, uint32_t& r1,
                                                  uint32_t& r2, uint32_t& r3,
                                                  uint32_t addr) {
    asm volatile("ldmatrix.sync.aligned.m8n8.x4.trans.shared.b16 {%0,%1,%2,%3}, [%4];"
                 : "=r"(r0), "=r"(r1), "=r"(r2), "=r"(r3) : "r"(addr));
}
__device__ __forceinline__ void mma_bf16(float* c, const uint32_t* a,
                                         uint32_t b0, uint32_t b1) {
    asm volatile(
        "mma.sync.aligned.m16n8k16.row.col.f32.bf16.bf16.f32 "
        "{%0,%1,%2,%3}, {%4,%5,%6,%7}, {%8,%9}, {%0,%1,%2,%3};"
        : "+f"(c[0]), "+f"(c[1]), "+f"(c[2]), "+f"(c[3])
        : "r"(a[0]), "r"(a[1]), "r"(a[2]), "r"(a[3]), "r"(b0), "r"(b1));
}
__device__ __forceinline__ void split2(float x, float y,
                                       uint32_t& hi, uint32_t& lo) {
    __nv_bfloat162 h, l;
    h.x = __float2bfloat16_rn(x);
    h.y = __float2bfloat16_rn(y);
    l.x = __float2bfloat16_rn(x - __bfloat162float(h.x));
    l.y = __float2bfloat16_rn(y - __bfloat162float(h.y));
    hi = *(uint32_t*)&h;
    lo = *(uint32_t*)&l;
}
#define GBAR(gid) asm volatile("bar.sync %0, %1;" :: "r"((gid) + 1), "r"(256) : "memory")

__global__ void wprep_kernel(const float* __restrict__ W,
                             __nv_bfloat16* __restrict__ hi,
                             __nv_bfloat16* __restrict__ lo) {
    int i = blockIdx.x * blockDim.x + threadIdx.x;
    if (i >= DD * DD) return;
    float w = W[i];
    __nv_bfloat16 h = __float2bfloat16_rn(w);
    hi[i] = h;
    lo[i] = __float2bfloat16_rn(w - __bfloat162float(h));
}

// ---------------------------------------------------------------------------
// Persistent fused MLP (unchanged from R8): 512 thr = 2 streams x 8 warps.
// ---------------------------------------------------------------------------
__global__ void __launch_bounds__(512, 1) mlp_fused_kernel(
    const float* __restrict__ X,
    const __nv_bfloat16* __restrict__ W1h, const __nv_bfloat16* __restrict__ W1l,
    const __nv_bfloat16* __restrict__ W2h, const __nv_bfloat16* __restrict__ W2l,
    const float* __restrict__ bias1, const float* __restrict__ bias2,
    uint4* __restrict__ H2h,
    int N, int T)
{
    extern __shared__ __align__(16) char smem[];
    const uint32_t sb = smem_u32(smem);
    const int tid  = threadIdx.x;
    const int g    = tid >> 8;
    const int tg   = tid & 255;
    const int warp = tg >> 5;
    const int lane = tid & 31;
    const int mg = warp & 1;
    const int ng = warp >> 1;

    {
        const __nv_bfloat16* wsrc[4] = {W1h, W1l, W2h, W2l};
        const uint32_t pdst[4] = {P_W1H, P_W1L, P_W2H, P_W2L};
#pragma unroll
        for (int i = 0; i < 16; i++) {
            int idx = tid + i * 512;
            int panel = idx >> 11;
            int rem   = idx & 2047;
            int row   = rem >> 4;
            int c     = rem & 15;
            uint4 v = ((const uint4*)(wsrc[panel] + row * DD))[c];
            *(uint4*)(smem + pdst[panel] + row * 256 +
                      ((c ^ (row & 7)) << 4)) = v;
        }
    }
    if (tid < DD) {
        ((float*)(smem + B1_OFF))[tid] = bias1[tid];
        ((float*)(smem + B2_OFF))[tid] = bias2[tid];
    }

    const uint32_t AH = A_BASE + g * 32768;
    const uint32_t AL = AH + 16384;

    int t = 2 * blockIdx.x + g;
    if (t < T) {
        const int row = tg >> 2, q4 = tg & 3;
        const int grow = t * TILE + row;
        const bool ok = grow < N;
        const float4* src = (const float4*)(X + (long long)grow * DD + q4 * 32);
        char* dh = smem + AH + row * 256;
        char* dl = smem + AL + row * 256;
        const int r7 = row & 7;
#pragma unroll
        for (int q = 0; q < 4; q++) {
            float4 a = ok ? src[2 * q]     : make_float4(0, 0, 0, 0);
            float4 b = ok ? src[2 * q + 1] : make_float4(0, 0, 0, 0);
            uint4 hv, lv;
            split2(a.x, a.y, hv.x, lv.x);
            split2(a.z, a.w, hv.y, lv.y);
            split2(b.x, b.y, hv.z, lv.z);
            split2(b.z, b.w, hv.w, lv.w);
            const uint32_t off = (((4 * q4 + q) ^ r7) << 4);
            *(uint4*)(dh + off) = hv;
            *(uint4*)(dl + off) = lv;
        }
    }
    __syncthreads();

    const int hA = lane >> 4;
    const int x7 = lane & 7;
    const uint32_t aRow = (uint32_t)(mg * 32 + (lane & 15));
    const uint32_t aHb = sb + AH + aRow * 256;
    const uint32_t aLb = sb + AL + aRow * 256;
    const uint32_t bRow = (uint32_t)(lane & 15) * 256;
    const uint32_t p1H = sb + P_W1H + bRow, p1L = sb + P_W1L + bRow;
    const uint32_t p2H = sb + P_W2H + bRow, p2L = sb + P_W2L + bRow;
    const float* sB1 = (const float*)(smem + B1_OFF);
    const float* sB2 = (const float*)(smem + B2_OFF);

    for (; t < T; t += 2 * NSM) {
        const int tn = t + 2 * NSM;
        const bool have_next = tn < T;

        float acc[2][4][4];
#pragma unroll
        for (int mt = 0; mt < 2; mt++)
#pragma unroll
            for (int nt = 0; nt < 4; nt++)
#pragma unroll
                for (int c = 0; c < 4; c++) acc[mt][nt][c] = 0.f;

        // ---- Layer 1 MMAs ----
#pragma unroll
        for (int ks = 0; ks < 8; ks++) {
            uint32_t ah[2][4], al[2][4];
#pragma unroll
            for (int mt = 0; mt < 2; mt++) {
                const uint32_t off = mt * 4096 + ((((2 * ks + hA) ^ x7)) << 4);
                ldmatrix_x4(ah[mt][0], ah[mt][1], ah[mt][2], ah[mt][3], aHb + off);
                ldmatrix_x4(al[mt][0], al[mt][1], al[mt][2], al[mt][3], aLb + off);
            }
            uint32_t bh[4][2], bl[4][2];
#pragma unroll
            for (int hf = 0; hf < 2; hf++) {
                const uint32_t off = ks * 4096 +
                    ((((4 * ng + 2 * hf + hA) ^ x7)) << 4);
                uint32_t r0, r1, r2, r3;
                ldmatrix_x4_trans(r0, r1, r2, r3, p1H + off);
                bh[2 * hf][0] = r0; bh[2 * hf][1] = r1;
                bh[2 * hf + 1][0] = r2; bh[2 * hf + 1][1] = r3;
                ldmatrix_x4_trans(r0, r1, r2, r3, p1L + off);
                bl[2 * hf][0] = r0; bl[2 * hf][1] = r1;
                bl[2 * hf + 1][0] = r2; bl[2 * hf + 1][1] = r3;
            }
#pragma unroll
            for (int mt = 0; mt < 2; mt++)
#pragma unroll
                for (int nt = 0; nt < 4; nt++) {
                    mma_bf16(acc[mt][nt], ah[mt], bh[nt][0], bh[nt][1]);
                    mma_bf16(acc[mt][nt], al[mt], bh[nt][0], bh[nt][1]);
                    mma_bf16(acc[mt][nt], ah[mt], bl[nt][0], bl[nt][1]);
                }
        }
        GBAR(g);

        // ---- Epilogue 1 ----
#pragma unroll
        for (int mt = 0; mt < 2; mt++) {
            const int r0 = mg * 32 + mt * 16 + (lane >> 2);
            const int r1 = r0 + 8;
#pragma unroll
            for (int nt = 0; nt < 4; nt++) {
                const int cc = ng * 32 + nt * 8 + (lane & 3) * 2;
                const float bx = sB1[cc], by = sB1[cc + 1];
                const float v0 = fmaxf(acc[mt][nt][0] + bx, 0.f);
                const float v1 = fmaxf(acc[mt][nt][1] + by, 0.f);
                const float v2 = fmaxf(acc[mt][nt][2] + bx, 0.f);
                const float v3 = fmaxf(acc[mt][nt][3] + by, 0.f);
                const uint32_t w0 = ((4 * ng + nt) ^ (r0 & 7)) * 16 + 4 * (lane & 3);
                const uint32_t w1 = ((4 * ng + nt) ^ (r1 & 7)) * 16 + 4 * (lane & 3);
                uint32_t hi, lo;
                split2(v0, v1, hi, lo);
                *(uint32_t*)(smem + AH + r0 * 256 + w0) = hi;
                *(uint32_t*)(smem + AL + r0 * 256 + w0) = lo;
                split2(v2, v3, hi, lo);
                *(uint32_t*)(smem + AH + r1 * 256 + w1) = hi;
                *(uint32_t*)(smem + AL + r1 * 256 + w1) = lo;
            }
        }
        GBAR(g);

        float4 xv[8];
        if (have_next) {
            const int row = tg >> 2, q4 = tg & 3;
            const int grow = tn * TILE + row;
            const bool ok = grow < N;
            const float4* src =
                (const float4*)(X + (long long)grow * DD + q4 * 32);
#pragma unroll
            for (int p = 0; p < 8; p++)
                xv[p] = ok ? src[p] : make_float4(0, 0, 0, 0);
        }

        // ---- Layer 2 MMAs ----
#pragma unroll
        for (int mt = 0; mt < 2; mt++)
#pragma unroll
            for (int nt = 0; nt < 4; nt++)
#pragma unroll
                for (int c = 0; c < 4; c++) acc[mt][nt][c] = 0.f;
#pragma unroll
        for (int ks = 0; ks < 8; ks++) {
            uint32_t ah[2][4], al[2][4];
#pragma unroll
            for (int mt = 0; mt < 2; mt++) {
                const uint32_t off = mt * 4096 + ((((2 * ks + hA) ^ x7)) << 4);
                ldmatrix_x4(ah[mt][0], ah[mt][1], ah[mt][2], ah[mt][3], aHb + off);
                ldmatrix_x4(al[mt][0], al[mt][1], al[mt][2], al[mt][3], aLb + off);
            }
            uint32_t bh[4][2], bl[4][2];
#pragma unroll
            for (int hf = 0; hf < 2; hf++) {
                const uint32_t off = ks * 4096 +
                    ((((4 * ng + 2 * hf + hA) ^ x7)) << 4);
                uint32_t r0, r1, r2, r3;
                ldmatrix_x4_trans(r0, r1, r2, r3, p2H + off);
                bh[2 * hf][0] = r0; bh[2 * hf][1] = r1;
                bh[2 * hf + 1][0] = r2; bh[2 * hf + 1][1] = r3;
                ldmatrix_x4_trans(r0, r1, r2, r3, p2L + off);
                bl[2 * hf][0] = r0; bl[2 * hf][1] = r1;
                bl[2 * hf + 1][0] = r2; bl[2 * hf + 1][1] = r3;
            }
#pragma unroll
            for (int mt = 0; mt < 2; mt++)
#pragma unroll
                for (int nt = 0; nt < 4; nt++) {
                    mma_bf16(acc[mt][nt], ah[mt], bh[nt][0], bh[nt][1]);
                    mma_bf16(acc[mt][nt], al[mt], bh[nt][0], bh[nt][1]);
                    mma_bf16(acc[mt][nt], ah[mt], bl[nt][0], bl[nt][1]);
                }
        }
        GBAR(g);

        // ---- Epilogue 2: h2 -> global fp16 ----
        {
            __half* H = (__half*)H2h;
            const int rowb = t * TILE + mg * 32;
#pragma unroll
            for (int mt = 0; mt < 2; mt++) {
                const int r0 = rowb + mt * 16 + (lane >> 2);
                const int r1 = r0 + 8;
                const bool ok0 = r0 < N, ok1 = r1 < N;
#pragma unroll
                for (int nt = 0; nt < 4; nt++) {
                    const int cc = ng * 32 + nt * 8 + (lane & 3) * 2;
                    const float bx = sB2[cc], by = sB2[cc + 1];
                    if (ok0) {
                        __half2 v = __floats2half2_rn(
                            fmaxf(acc[mt][nt][0] + bx, 0.f),
                            fmaxf(acc[mt][nt][1] + by, 0.f));
                        *(__half2*)(H + (long long)r0 * DD + cc) = v;
                    }
                    if (ok1) {
                        __half2 v = __floats2half2_rn(
                            fmaxf(acc[mt][nt][2] + bx, 0.f),
                            fmaxf(acc[mt][nt][3] + by, 0.f));
                        *(__half2*)(H + (long long)r1 * DD + cc) = v;
                    }
                }
            }
        }

        if (have_next) {
            const int row = tg >> 2, q4 = tg & 3;
            char* dh = smem + AH + row * 256;
            char* dl = smem + AL + row * 256;
            const int r7 = row & 7;
#pragma unroll
            for (int q = 0; q < 4; q++) {
                uint4 hv, lv;
                split2(xv[2 * q].x, xv[2 * q].y, hv.x, lv.x);
                split2(xv[2 * q].z, xv[2 * q].w, hv.y, lv.y);
                split2(xv[2 * q + 1].x, xv[2 * q + 1].y, hv.z, lv.z);
                split2(xv[2 * q + 1].z, xv[2 * q + 1].w, hv.w, lv.w);
                const uint32_t off = (((4 * q4 + q) ^ r7) << 4);
                *(uint4*)(dh + off) = hv;
                *(uint4*)(dl + off) = lv;
            }
        }
        GBAR(g);
    }
}

// ---------------------------------------------------------------------------
// Edge decode, R9: 16 lanes per edge, 4 edges per warp, uint4 (16B) loads.
// Lane (eh=lane>>4, el=lane&15) handles edges base+eh and base+eh+2;
// el indexes 16B chunks of the 256B fp16 node row.
// ---------------------------------------------------------------------------
__device__ __forceinline__ float dot16B(uint4 a, uint4 b) {
    float2 s0 = __half22float2(*(const __half2*)&a.x);
    float2 t0 = __half22float2(*(const __half2*)&b.x);
    float2 s1 = __half22float2(*(const __half2*)&a.y);
    float2 t1 = __half22float2(*(const __half2*)&b.y);
    float2 s2 = __half22float2(*(const __half2*)&a.z);
    float2 t2 = __half22float2(*(const __half2*)&b.z);
    float2 s3 = __half22float2(*(const __half2*)&a.w);
    float2 t3 = __half22float2(*(const __half2*)&b.w);
    float r = s0.x * t0.x;
    r = fmaf(s0.y, t0.y, r);
    r = fmaf(s1.x, t1.x, r);
    r = fmaf(s1.y, t1.y, r);
    r = fmaf(s2.x, t2.x, r);
    r = fmaf(s2.y, t2.y, r);
    r = fmaf(s3.x, t3.x, r);
    r = fmaf(s3.y, t3.y, r);
    return r;
}

__global__ void __launch_bounds__(256) edge_dot_kernel(
    const uint4* __restrict__ H16,
    const int* __restrict__ edge_index,
    const int* __restrict__ lbl,
    float* __restrict__ out,
    float* __restrict__ lblout,
    int E, int N)
{
    const int gwarp = (blockIdx.x * blockDim.x + threadIdx.x) >> 5;
    const int lane  = threadIdx.x & 31;
    const int el = lane & 15;
    const int eh = lane >> 4;
    const int base = gwarp * 4;
    if (base >= E) return;

    const int eA = base + eh;
    const int eB = base + eh + 2;
    const bool okA = eA < E, okB = eB < E;
    const int iA = okA ? eA : 0;
    const int iB = okB ? eB : 0;

    int sA = edge_index[iA], dA = edge_index[E + iA];
    int sB = edge_index[iB], dB = edge_index[E + iB];
    sA = min(max(sA, 0), N - 1); dA = min(max(dA, 0), N - 1);
    sB = min(max(sB, 0), N - 1); dB = min(max(dB, 0), N - 1);

    // 4 independent 16B gathers (row = 16 uint4).
    const uint4 vsA = H16[sA * 16 + el];
    const uint4 vdA = H16[dA * 16 + el];
    const uint4 vsB = H16[sB * 16 + el];
    const uint4 vdB = H16[dB * 16 + el];

    float rA = dot16B(vsA, vdA);
    float rB = dot16B(vsB, vdB);

    // Reduce over the 16-lane group (eh bit preserved by xor < 16).
#pragma unroll
    for (int o = 8; o > 0; o >>= 1) {
        rA += __shfl_xor_sync(0xFFFFFFFFu, rA, o);
        rB += __shfl_xor_sync(0xFFFFFFFFu, rB, o);
    }

    if (el == 0) {
        if (okA) out[eA] = rA;
        if (okB) out[eB] = rB;
    }
    if (lblout && el == 1) {
        if (okA) lblout[eA] = (float)lbl[eA];
        if (okB) lblout[eB] = (float)lbl[eB];
    }
}

extern "C" void kernel_launch(void* const* d_in, const int* in_sizes, int n_in,
                              void* d_out, int out_size)
{
    const float* x   = (const float*)d_in[0];
    const int*   ei  = (const int*)d_in[1];
    const int*   lbl = (const int*)d_in[2];
    const float* W1  = (const float*)d_in[3];
    const float* b1  = (const float*)d_in[4];
    const float* W2  = (const float*)d_in[5];
    const float* b2  = (const float*)d_in[6];

    int N = in_sizes[0] / DD;   // 100000
    int E = in_sizes[2];        // 500000

    uint4* h2h;
    __nv_bfloat16 *w1hi, *w1lo, *w2hi, *w2lo;
    cudaGetSymbolAddress((void**)&h2h, g_h2h);
    cudaGetSymbolAddress((void**)&w1hi, g_w1hi);
    cudaGetSymbolAddress((void**)&w1lo, g_w1lo);
    cudaGetSymbolAddress((void**)&w2hi, g_w2hi);
    cudaGetSymbolAddress((void**)&w2lo, g_w2lo);

    cudaFuncSetAttribute(mlp_fused_kernel,
                         cudaFuncAttributeMaxDynamicSharedMemorySize, SMEM_TOTAL);

    wprep_kernel<<<(DD * DD + 255) / 256, 256>>>(W1, w1hi, w1lo);
    wprep_kernel<<<(DD * DD + 255) / 256, 256>>>(W2, w2hi, w2lo);

    int T = (N + TILE - 1) / TILE;
    mlp_fused_kernel<<<NSM, 512, SMEM_TOTAL>>>(x, w1hi, w1lo, w2hi, w2lo,
                                               b1, b2, h2h, N, T);

    float* out = (float*)d_out;
    float* lblout = (out_size >= 2 * E) ? out + E : nullptr;
    int warps  = (E + 3) / 4;            // 4 edges per warp
    int blocks = (warps + 7) / 8;        // 8 warps per block
    edge_dot_kernel<<<blocks, 256>>>(h2h, ei, lbl, out, lblout, E, N);
}

// round 10
// speedup vs baseline: 3.6225x; 1.1247x over previous
#include <cuda_runtime.h>
#include <cuda_fp16.h>
#include <cstdint>

// ---------------------------------------------------------------------------
// GNNTransductiveEdgeHead, R10:
//  - MLP: persistent CTA, two 8-warp streams, 128-row tiles, fp16 2-term
//    split GEMM (Xhi@Whi + Xlo@Whi, W rounded to fp16), h2 stored fp16.
//  - edge dot: 16 lanes/edge, 4 edges/warp (unchanged from R9).
// ---------------------------------------------------------------------------

#define DD 128
#define TILE 128           // rows per stream-tile
#define MAX_NODES 100000
#define NSM 148

// SMEM layout (bytes)
#define P_W1H 0
#define P_W2H 32768
#define A_BASE 65536       // stream g: hi at A_BASE+g*65536, lo at +32768
#define B1_OFF 196608
#define B2_OFF 197120
#define SMEM_TOTAL 197632

__device__ uint4 g_h2h[MAX_NODES * 16];          // h2 as fp16, 256B per node
__device__ __half g_w1h[DD * DD];
__device__ __half g_w2h[DD * DD];

__device__ __forceinline__ uint32_t smem_u32(const void* p) {
    uint32_t a;
    asm("{ .reg .u64 t; cvta.to.shared.u64 t, %1; cvt.u32.u64 %0, t; }"
        : "=r"(a) : "l"(p));
    return a;
}
__device__ __forceinline__ void ldmatrix_x4(uint32_t& r0, uint32_t& r1,
                                            uint32_t& r2, uint32_t& r3,
                                            uint32_t addr) {
    asm volatile("ldmatrix.sync.aligned.m8n8.x4.shared.b16 {%0,%1,%2,%3}, [%4];"
                 : "=r"(r0), "=r"(r1), "=r"(r2), "=r"(r3) : "r"(addr));
}
__device__ __forceinline__ void ldmatrix_x4_trans(uint32_t& r0, uint32_t& r1,
                                                  uint32_t& r2, uint32_t& r3,
                                                  uint32_t addr) {
    asm volatile("ldmatrix.sync.aligned.m8n8.x4.trans.shared.b16 {%0,%1,%2,%3}, [%4];"
                 : "=r"(r0), "=r"(r1), "=r"(r2), "=r"(r3) : "r"(addr));
}
__device__ __forceinline__ void mma_f16(float* c, const uint32_t* a,
                                        uint32_t b0, uint32_t b1) {
    asm volatile(
        "mma.sync.aligned.m16n8k16.row.col.f32.f16.f16.f32 "
        "{%0,%1,%2,%3}, {%4,%5,%6,%7}, {%8,%9}, {%0,%1,%2,%3};"
        : "+f"(c[0]), "+f"(c[1]), "+f"(c[2]), "+f"(c[3])
        : "r"(a[0]), "r"(a[1]), "r"(a[2]), "r"(a[3]), "r"(b0), "r"(b1));
}
__device__ __forceinline__ void split2h(float x, float y,
                                        uint32_t& hi, uint32_t& lo) {
    __half2 h, l;
    h.x = __float2half_rn(x);
    h.y = __float2half_rn(y);
    l.x = __float2half_rn(x - __half2float(h.x));
    l.y = __float2half_rn(y - __half2float(h.y));
    hi = *(uint32_t*)&h;
    lo = *(uint32_t*)&l;
}
#define GBAR(gid) asm volatile("bar.sync %0, %1;" :: "r"((gid) + 1), "r"(256) : "memory")

__global__ void wprep_kernel(const float* __restrict__ W,
                             __half* __restrict__ hi) {
    int i = blockIdx.x * blockDim.x + threadIdx.x;
    if (i < DD * DD) hi[i] = __float2half_rn(W[i]);
}

// 2-term fp16 MMA over one staged A tile (hi/lo) vs one W-hi panel.
__device__ __forceinline__ void mma_layer(float acc[4][4][4],
                                          uint32_t aHb, uint32_t aLb,
                                          uint32_t pB,
                                          int hA, int x7, int ng) {
#pragma unroll
    for (int ks = 0; ks < 8; ks++) {
        uint32_t ah[4][4], al[4][4];
#pragma unroll
        for (int mt = 0; mt < 4; mt++) {
            const uint32_t off = mt * 4096 + ((((2 * ks + hA) ^ x7)) << 4);
            ldmatrix_x4(ah[mt][0], ah[mt][1], ah[mt][2], ah[mt][3], aHb + off);
            ldmatrix_x4(al[mt][0], al[mt][1], al[mt][2], al[mt][3], aLb + off);
        }
        uint32_t bh[4][2];
#pragma unroll
        for (int hf = 0; hf < 2; hf++) {
            const uint32_t off = ks * 4096 +
                ((((4 * ng + 2 * hf + hA) ^ x7)) << 4);
            uint32_t r0, r1, r2, r3;
            ldmatrix_x4_trans(r0, r1, r2, r3, pB + off);
            bh[2 * hf][0] = r0; bh[2 * hf][1] = r1;
            bh[2 * hf + 1][0] = r2; bh[2 * hf + 1][1] = r3;
        }
#pragma unroll
        for (int mt = 0; mt < 4; mt++)
#pragma unroll
            for (int nt = 0; nt < 4; nt++) {
                mma_f16(acc[mt][nt], ah[mt], bh[nt][0], bh[nt][1]);
                mma_f16(acc[mt][nt], al[mt], bh[nt][0], bh[nt][1]);
            }
    }
}

// ---------------------------------------------------------------------------
// Persistent fused MLP: 512 thr = 2 streams x 8 warps; stream tile 128 rows;
// warp (mg=w&1, ng=w>>1) owns rows [64mg,64mg+64) x cols [32ng,32ng+32).
// ---------------------------------------------------------------------------
__global__ void __launch_bounds__(512, 1) mlp_fused_kernel(
    const float* __restrict__ X,
    const __half* __restrict__ W1h, const __half* __restrict__ W2h,
    const float* __restrict__ bias1, const float* __restrict__ bias2,
    uint4* __restrict__ H2h,
    int N, int T)
{
    extern __shared__ __align__(16) char smem[];
    const uint32_t sb = smem_u32(smem);
    const int tid  = threadIdx.x;
    const int g    = tid >> 8;        // stream 0/1
    const int tg   = tid & 255;
    const int warp = tg >> 5;
    const int lane = tid & 31;
    const int mg = warp & 1;
    const int ng = warp >> 1;

    // --- Prologue: stage swizzled W panels (fp16 hi only) ---
    {
        const __half* wsrc[2] = {W1h, W2h};
        const uint32_t pdst[2] = {P_W1H, P_W2H};
#pragma unroll
        for (int i = 0; i < 8; i++) {
            int idx = tid + i * 512;          // 4096 chunks total
            int panel = idx >> 11;
            int rem   = idx & 2047;
            int row   = rem >> 4;
            int c     = rem & 15;
            uint4 v = ((const uint4*)(wsrc[panel] + row * DD))[c];
            *(uint4*)(smem + pdst[panel] + row * 256 +
                      ((c ^ (row & 7)) << 4)) = v;
        }
    }
    if (tid < DD) {
        ((float*)(smem + B1_OFF))[tid] = bias1[tid];
        ((float*)(smem + B2_OFF))[tid] = bias2[tid];
    }

    const uint32_t AHI = A_BASE + g * 65536;
    const uint32_t ALO = AHI + 32768;

    // Stage first tile: thread owns row tg>>1, 64-float half (tg&1).
    int t = 2 * blockIdx.x + g;
    if (t < T) {
        const int row = tg >> 1, hf = tg & 1;
        const int grow = t * TILE + row;
        const bool ok = grow < N;
        const float4* src = (const float4*)(X + (long long)grow * DD + hf * 64);
        char* dh = smem + AHI + row * 256;
        char* dl = smem + ALO + row * 256;
        const int r7 = row & 7;
#pragma unroll
        for (int q = 0; q < 8; q++) {
            float4 a = ok ? src[2 * q]     : make_float4(0, 0, 0, 0);
            float4 b = ok ? src[2 * q + 1] : make_float4(0, 0, 0, 0);
            uint4 hv, lv;
            split2h(a.x, a.y, hv.x, lv.x);
            split2h(a.z, a.w, hv.y, lv.y);
            split2h(b.x, b.y, hv.z, lv.z);
            split2h(b.z, b.w, hv.w, lv.w);
            const uint32_t off = (((8 * hf + q) ^ r7) << 4);
            *(uint4*)(dh + off) = hv;
            *(uint4*)(dl + off) = lv;
        }
    }
    __syncthreads();   // W panels + first tiles visible

    const int hA = lane >> 4;
    const int x7 = lane & 7;
    const uint32_t aRow = (uint32_t)(mg * 64 + (lane & 15));
    const uint32_t aHb = sb + AHI + aRow * 256;
    const uint32_t aLb = sb + ALO + aRow * 256;
    const uint32_t bRow = (uint32_t)(lane & 15) * 256;
    const uint32_t p1 = sb + P_W1H + bRow;
    const uint32_t p2 = sb + P_W2H + bRow;
    const float* sB1 = (const float*)(smem + B1_OFF);
    const float* sB2 = (const float*)(smem + B2_OFF);

    for (; t < T; t += 2 * NSM) {
        const int tn = t + 2 * NSM;
        const bool have_next = tn < T;

        float acc[4][4][4];
#pragma unroll
        for (int mt = 0; mt < 4; mt++)
#pragma unroll
            for (int nt = 0; nt < 4; nt++)
#pragma unroll
                for (int c = 0; c < 4; c++) acc[mt][nt][c] = 0.f;

        // ---- Layer 1 MMAs ----
        mma_layer(acc, aHb, aLb, p1, hA, x7, ng);
        GBAR(g);

        // ---- Epilogue 1: h1 = relu(acc+b1) split-fp16 -> A buffer ----
#pragma unroll
        for (int mt = 0; mt < 4; mt++) {
            const int r0 = mg * 64 + mt * 16 + (lane >> 2);
            const int r1 = r0 + 8;
#pragma unroll
            for (int nt = 0; nt < 4; nt++) {
                const int cc = ng * 32 + nt * 8 + (lane & 3) * 2;
                const float bx = sB1[cc], by = sB1[cc + 1];
                const float v0 = fmaxf(acc[mt][nt][0] + bx, 0.f);
                const float v1 = fmaxf(acc[mt][nt][1] + by, 0.f);
                const float v2 = fmaxf(acc[mt][nt][2] + bx, 0.f);
                const float v3 = fmaxf(acc[mt][nt][3] + by, 0.f);
                const uint32_t w0 = ((4 * ng + nt) ^ (r0 & 7)) * 16 + 4 * (lane & 3);
                const uint32_t w1 = ((4 * ng + nt) ^ (r1 & 7)) * 16 + 4 * (lane & 3);
                uint32_t hi, lo;
                split2h(v0, v1, hi, lo);
                *(uint32_t*)(smem + AHI + r0 * 256 + w0) = hi;
                *(uint32_t*)(smem + ALO + r0 * 256 + w0) = lo;
                split2h(v2, v3, hi, lo);
                *(uint32_t*)(smem + AHI + r1 * 256 + w1) = hi;
                *(uint32_t*)(smem + ALO + r1 * 256 + w1) = lo;
            }
        }
        GBAR(g);

        // ---- Layer 2 MMAs ----
#pragma unroll
        for (int mt = 0; mt < 4; mt++)
#pragma unroll
            for (int nt = 0; nt < 4; nt++)
#pragma unroll
                for (int c = 0; c < 4; c++) acc[mt][nt][c] = 0.f;
        mma_layer(acc, aHb, aLb, p2, hA, x7, ng);
        GBAR(g);   // all warps past A reads -> A free for restage

        // ---- Stage next tile (A buffer) ----
        if (have_next) {
            const int row = tg >> 1, hf = tg & 1;
            const int grow = tn * TILE + row;
            const bool ok = grow < N;
            const float4* src =
                (const float4*)(X + (long long)grow * DD + hf * 64);
            char* dh = smem + AHI + row * 256;
            char* dl = smem + ALO + row * 256;
            const int r7 = row & 7;
#pragma unroll
            for (int q = 0; q < 8; q++) {
                float4 a = ok ? src[2 * q]     : make_float4(0, 0, 0, 0);
                float4 b = ok ? src[2 * q + 1] : make_float4(0, 0, 0, 0);
                uint4 hv, lv;
                split2h(a.x, a.y, hv.x, lv.x);
                split2h(a.z, a.w, hv.y, lv.y);
                split2h(b.x, b.y, hv.z, lv.z);
                split2h(b.z, b.w, hv.w, lv.w);
                const uint32_t off = (((8 * hf + q) ^ r7) << 4);
                *(uint4*)(dh + off) = hv;
                *(uint4*)(dl + off) = lv;
            }
        }

        // ---- Epilogue 2: h2 = relu(acc+b2) -> global fp16 ----
        {
            __half* H = (__half*)H2h;
            const int rowb = t * TILE + mg * 64;
#pragma unroll
            for (int mt = 0; mt < 4; mt++) {
                const int r0 = rowb + mt * 16 + (lane >> 2);
                const int r1 = r0 + 8;
                const bool ok0 = r0 < N, ok1 = r1 < N;
#pragma unroll
                for (int nt = 0; nt < 4; nt++) {
                    const int cc = ng * 32 + nt * 8 + (lane & 3) * 2;
                    const float bx = sB2[cc], by = sB2[cc + 1];
                    if (ok0) {
                        __half2 v = __floats2half2_rn(
                            fmaxf(acc[mt][nt][0] + bx, 0.f),
                            fmaxf(acc[mt][nt][1] + by, 0.f));
                        *(__half2*)(H + (long long)r0 * DD + cc) = v;
                    }
                    if (ok1) {
                        __half2 v = __floats2half2_rn(
                            fmaxf(acc[mt][nt][2] + bx, 0.f),
                            fmaxf(acc[mt][nt][3] + by, 0.f));
                        *(__half2*)(H + (long long)r1 * DD + cc) = v;
                    }
                }
            }
        }
        GBAR(g);
    }
}

// ---------------------------------------------------------------------------
// Edge decode (R9): 16 lanes per edge, 4 edges per warp, uint4 loads.
// ---------------------------------------------------------------------------
__device__ __forceinline__ float dot16B(uint4 a, uint4 b) {
    float2 s0 = __half22float2(*(const __half2*)&a.x);
    float2 t0 = __half22float2(*(const __half2*)&b.x);
    float2 s1 = __half22float2(*(const __half2*)&a.y);
    float2 t1 = __half22float2(*(const __half2*)&b.y);
    float2 s2 = __half22float2(*(const __half2*)&a.z);
    float2 t2 = __half22float2(*(const __half2*)&b.z);
    float2 s3 = __half22float2(*(const __half2*)&a.w);
    float2 t3 = __half22float2(*(const __half2*)&b.w);
    float r = s0.x * t0.x;
    r = fmaf(s0.y, t0.y, r);
    r = fmaf(s1.x, t1.x, r);
    r = fmaf(s1.y, t1.y, r);
    r = fmaf(s2.x, t2.x, r);
    r = fmaf(s2.y, t2.y, r);
    r = fmaf(s3.x, t3.x, r);
    r = fmaf(s3.y, t3.y, r);
    return r;
}

__global__ void __launch_bounds__(256) edge_dot_kernel(
    const uint4* __restrict__ H16,
    const int* __restrict__ edge_index,
    const int* __restrict__ lbl,
    float* __restrict__ out,
    float* __restrict__ lblout,
    int E, int N)
{
    const int gwarp = (blockIdx.x * blockDim.x + threadIdx.x) >> 5;
    const int lane  = threadIdx.x & 31;
    const int el = lane & 15;
    const int eh = lane >> 4;
    const int base = gwarp * 4;
    if (base >= E) return;

    const int eA = base + eh;
    const int eB = base + eh + 2;
    const bool okA = eA < E, okB = eB < E;
    const int iA = okA ? eA : 0;
    const int iB = okB ? eB : 0;

    int sA = edge_index[iA], dA = edge_index[E + iA];
    int sB = edge_index[iB], dB = edge_index[E + iB];
    sA = min(max(sA, 0), N - 1); dA = min(max(dA, 0), N - 1);
    sB = min(max(sB, 0), N - 1); dB = min(max(dB, 0), N - 1);

    const uint4 vsA = H16[sA * 16 + el];
    const uint4 vdA = H16[dA * 16 + el];
    const uint4 vsB = H16[sB * 16 + el];
    const uint4 vdB = H16[dB * 16 + el];

    float rA = dot16B(vsA, vdA);
    float rB = dot16B(vsB, vdB);

#pragma unroll
    for (int o = 8; o > 0; o >>= 1) {
        rA += __shfl_xor_sync(0xFFFFFFFFu, rA, o);
        rB += __shfl_xor_sync(0xFFFFFFFFu, rB, o);
    }

    if (el == 0) {
        if (okA) out[eA] = rA;
        if (okB) out[eB] = rB;
    }
    if (lblout && el == 1) {
        if (okA) lblout[eA] = (float)lbl[eA];
        if (okB) lblout[eB] = (float)lbl[eB];
    }
}

extern "C" void kernel_launch(void* const* d_in, const int* in_sizes, int n_in,
                              void* d_out, int out_size)
{
    const float* x   = (const float*)d_in[0];
    const int*   ei  = (const int*)d_in[1];
    const int*   lbl = (const int*)d_in[2];
    const float* W1  = (const float*)d_in[3];
    const float* b1  = (const float*)d_in[4];
    const float* W2  = (const float*)d_in[5];
    const float* b2  = (const float*)d_in[6];

    int N = in_sizes[0] / DD;   // 100000
    int E = in_sizes[2];        // 500000

    uint4* h2h;
    __half *w1h, *w2h;
    cudaGetSymbolAddress((void**)&h2h, g_h2h);
    cudaGetSymbolAddress((void**)&w1h, g_w1h);
    cudaGetSymbolAddress((void**)&w2h, g_w2h);

    cudaFuncSetAttribute(mlp_fused_kernel,
                         cudaFuncAttributeMaxDynamicSharedMemorySize, SMEM_TOTAL);

    wprep_kernel<<<(DD * DD + 255) / 256, 256>>>(W1, w1h);
    wprep_kernel<<<(DD * DD + 255) / 256, 256>>>(W2, w2h);

    int T = (N + TILE - 1) / TILE;
    mlp_fused_kernel<<<NSM, 512, SMEM_TOTAL>>>(x, w1h, w2h, b1, b2, h2h, N, T);

    float* out = (float*)d_out;
    float* lblout = (out_size >= 2 * E) ? out + E : nullptr;
    int warps  = (E + 3) / 4;            // 4 edges per warp
    int blocks = (warps + 7) / 8;        // 8 warps per block
    edge_dot_kernel<<<blocks, 256>>>(h2h, ei, lbl, out, lblout, E, N);
}

// round 11
// speedup vs baseline: 4.5302x; 1.2506x over previous
#include <cuda_runtime.h>
#include <cuda_fp16.h>
#include <cstdint>

// ---------------------------------------------------------------------------
// GNNTransductiveEdgeHead, R11:
//  - MLP: persistent CTA, two 8-warp streams, 128-row tiles, PLAIN fp16 GEMM
//    (fp32 accumulate). W-side fp16 rounding already bounds error at ~1e-4;
//    the X-side lo term was numerically redundant. h1/h2 stored fp16.
//  - edge dot: 16 lanes/edge, 4 edges/warp (unchanged from R9).
// ---------------------------------------------------------------------------

#define DD 128
#define TILE 128           // rows per stream-tile
#define MAX_NODES 100000
#define NSM 148

// SMEM layout (bytes): rows are 128 fp16 = 256B, XOR-swizzled 16B chunks.
#define P_W1H 0
#define P_W2H 32768
#define A_BASE 65536       // stream g: A_BASE + g*32768
#define B1_OFF 131072
#define B2_OFF 131584
#define SMEM_TOTAL 132096

__device__ uint4 g_h2h[MAX_NODES * 16];          // h2 as fp16, 256B per node
__device__ __half g_w1h[DD * DD];
__device__ __half g_w2h[DD * DD];

__device__ __forceinline__ uint32_t smem_u32(const void* p) {
    uint32_t a;
    asm("{ .reg .u64 t; cvta.to.shared.u64 t, %1; cvt.u32.u64 %0, t; }"
        : "=r"(a) : "l"(p));
    return a;
}
__device__ __forceinline__ void ldmatrix_x4(uint32_t& r0, uint32_t& r1,
                                            uint32_t& r2, uint32_t& r3,
                                            uint32_t addr) {
    asm volatile("ldmatrix.sync.aligned.m8n8.x4.shared.b16 {%0,%1,%2,%3}, [%4];"
                 : "=r"(r0), "=r"(r1), "=r"(r2), "=r"(r3) : "r"(addr));
}
__device__ __forceinline__ void ldmatrix_x4_trans(uint32_t& r0, uint32_t& r1,
                                                  uint32_t& r2, uint32_t& r3,
                                                  uint32_t addr) {
    asm volatile("ldmatrix.sync.aligned.m8n8.x4.trans.shared.b16 {%0,%1,%2,%3}, [%4];"
                 : "=r"(r0), "=r"(r1), "=r"(r2), "=r"(r3) : "r"(addr));
}
__device__ __forceinline__ void mma_f16(float* c, const uint32_t* a,
                                        uint32_t b0, uint32_t b1) {
    asm volatile(
        "mma.sync.aligned.m16n8k16.row.col.f32.f16.f16.f32 "
        "{%0,%1,%2,%3}, {%4,%5,%6,%7}, {%8,%9}, {%0,%1,%2,%3};"
        : "+f"(c[0]), "+f"(c[1]), "+f"(c[2]), "+f"(c[3])
        : "r"(a[0]), "r"(a[1]), "r"(a[2]), "r"(a[3]), "r"(b0), "r"(b1));
}
__device__ __forceinline__ uint32_t packh2(float x, float y) {
    __half2 h = __floats2half2_rn(x, y);
    return *(uint32_t*)&h;
}
#define GBAR(gid) asm volatile("bar.sync %0, %1;" :: "r"((gid) + 1), "r"(256) : "memory")

__global__ void wprep_kernel(const float* __restrict__ W1,
                             const float* __restrict__ W2,
                             __half* __restrict__ w1h,
                             __half* __restrict__ w2h) {
    int i = blockIdx.x * blockDim.x + threadIdx.x;
    if (i < DD * DD)              w1h[i] = __float2half_rn(W1[i]);
    else if (i < 2 * DD * DD)     w2h[i - DD * DD] = __float2half_rn(W2[i - DD * DD]);
}

// fp16 MMA over one staged A tile vs one W panel: 8 ks x (6 LDSM + 16 HMMA).
__device__ __forceinline__ void mma_layer(float acc[4][4][4],
                                          uint32_t aB, uint32_t pB,
                                          int hA, int x7, int ng) {
#pragma unroll
    for (int ks = 0; ks < 8; ks++) {
        uint32_t ah[4][4];
#pragma unroll
        for (int mt = 0; mt < 4; mt++) {
            const uint32_t off = mt * 4096 + ((((2 * ks + hA) ^ x7)) << 4);
            ldmatrix_x4(ah[mt][0], ah[mt][1], ah[mt][2], ah[mt][3], aB + off);
        }
        uint32_t bh[4][2];
#pragma unroll
        for (int hf = 0; hf < 2; hf++) {
            const uint32_t off = ks * 4096 +
                ((((4 * ng + 2 * hf + hA) ^ x7)) << 4);
            uint32_t r0, r1, r2, r3;
            ldmatrix_x4_trans(r0, r1, r2, r3, pB + off);
            bh[2 * hf][0] = r0; bh[2 * hf][1] = r1;
            bh[2 * hf + 1][0] = r2; bh[2 * hf + 1][1] = r3;
        }
#pragma unroll
        for (int mt = 0; mt < 4; mt++)
#pragma unroll
            for (int nt = 0; nt < 4; nt++)
                mma_f16(acc[mt][nt], ah[mt], bh[nt][0], bh[nt][1]);
    }
}

// ---------------------------------------------------------------------------
// Persistent fused MLP: 512 thr = 2 streams x 8 warps; stream tile 128 rows;
// warp (mg=w&1, ng=w>>1) owns rows [64mg,64mg+64) x cols [32ng,32ng+32).
// ---------------------------------------------------------------------------
__global__ void __launch_bounds__(512, 1) mlp_fused_kernel(
    const float* __restrict__ X,
    const __half* __restrict__ W1h, const __half* __restrict__ W2h,
    const float* __restrict__ bias1, const float* __restrict__ bias2,
    uint4* __restrict__ H2h,
    int N, int T)
{
    extern __shared__ __align__(16) char smem[];
    const uint32_t sb = smem_u32(smem);
    const int tid  = threadIdx.x;
    const int g    = tid >> 8;        // stream 0/1
    const int tg   = tid & 255;
    const int warp = tg >> 5;
    const int lane = tid & 31;
    const int mg = warp & 1;
    const int ng = warp >> 1;

    // --- Prologue: stage swizzled W panels (fp16) ---
    {
        const __half* wsrc[2] = {W1h, W2h};
        const uint32_t pdst[2] = {P_W1H, P_W2H};
#pragma unroll
        for (int i = 0; i < 8; i++) {
            int idx = tid + i * 512;          // 4096 chunks total
            int panel = idx >> 11;
            int rem   = idx & 2047;
            int row   = rem >> 4;
            int c     = rem & 15;
            uint4 v = ((const uint4*)(wsrc[panel] + row * DD))[c];
            *(uint4*)(smem + pdst[panel] + row * 256 +
                      ((c ^ (row & 7)) << 4)) = v;
        }
    }
    if (tid < DD) {
        ((float*)(smem + B1_OFF))[tid] = bias1[tid];
        ((float*)(smem + B2_OFF))[tid] = bias2[tid];
    }

    const uint32_t AB = A_BASE + g * 32768;

    // Stage first tile: thread owns row tg>>1, 64-float half (tg&1).
    int t = 2 * blockIdx.x + g;
    if (t < T) {
        const int row = tg >> 1, hf = tg & 1;
        const int grow = t * TILE + row;
        const bool ok = grow < N;
        const float4* src = (const float4*)(X + (long long)grow * DD + hf * 64);
        char* d = smem + AB + row * 256;
        const int r7 = row & 7;
#pragma unroll
        for (int q = 0; q < 8; q++) {
            float4 a = ok ? src[2 * q]     : make_float4(0, 0, 0, 0);
            float4 b = ok ? src[2 * q + 1] : make_float4(0, 0, 0, 0);
            uint4 v;
            v.x = packh2(a.x, a.y);
            v.y = packh2(a.z, a.w);
            v.z = packh2(b.x, b.y);
            v.w = packh2(b.z, b.w);
            *(uint4*)(d + (((8 * hf + q) ^ r7) << 4)) = v;
        }
    }
    __syncthreads();   // W panels + first tiles visible

    const int hA = lane >> 4;
    const int x7 = lane & 7;
    const uint32_t aRow = (uint32_t)(mg * 64 + (lane & 15));
    const uint32_t aB = sb + AB + aRow * 256;
    const uint32_t bRow = (uint32_t)(lane & 15) * 256;
    const uint32_t p1 = sb + P_W1H + bRow;
    const uint32_t p2 = sb + P_W2H + bRow;
    const float* sB1 = (const float*)(smem + B1_OFF);
    const float* sB2 = (const float*)(smem + B2_OFF);

    for (; t < T; t += 2 * NSM) {
        const int tn = t + 2 * NSM;
        const bool have_next = tn < T;

        float acc[4][4][4];
#pragma unroll
        for (int mt = 0; mt < 4; mt++)
#pragma unroll
            for (int nt = 0; nt < 4; nt++)
#pragma unroll
                for (int c = 0; c < 4; c++) acc[mt][nt][c] = 0.f;

        // ---- Layer 1 MMAs ----
        mma_layer(acc, aB, p1, hA, x7, ng);
        GBAR(g);   // stream done reading A

        // ---- Epilogue 1: h1 = relu(acc+b1) -> fp16 A buffer ----
#pragma unroll
        for (int mt = 0; mt < 4; mt++) {
            const int r0 = mg * 64 + mt * 16 + (lane >> 2);
            const int r1 = r0 + 8;
#pragma unroll
            for (int nt = 0; nt < 4; nt++) {
                const int cc = ng * 32 + nt * 8 + (lane & 3) * 2;
                const float bx = sB1[cc], by = sB1[cc + 1];
                const uint32_t w0 = ((4 * ng + nt) ^ (r0 & 7)) * 16 + 4 * (lane & 3);
                const uint32_t w1 = ((4 * ng + nt) ^ (r1 & 7)) * 16 + 4 * (lane & 3);
                *(uint32_t*)(smem + AB + r0 * 256 + w0) =
                    packh2(fmaxf(acc[mt][nt][0] + bx, 0.f),
                           fmaxf(acc[mt][nt][1] + by, 0.f));
                *(uint32_t*)(smem + AB + r1 * 256 + w1) =
                    packh2(fmaxf(acc[mt][nt][2] + bx, 0.f),
                           fmaxf(acc[mt][nt][3] + by, 0.f));
            }
        }
        GBAR(g);   // h1 visible

        // ---- Layer 2 MMAs ----
#pragma unroll
        for (int mt = 0; mt < 4; mt++)
#pragma unroll
            for (int nt = 0; nt < 4; nt++)
#pragma unroll
                for (int c = 0; c < 4; c++) acc[mt][nt][c] = 0.f;
        mma_layer(acc, aB, p2, hA, x7, ng);
        GBAR(g);   // A free for restage

        // ---- Stage next tile ----
        if (have_next) {
            const int row = tg >> 1, hf = tg & 1;
            const int grow = tn * TILE + row;
            const bool ok = grow < N;
            const float4* src =
                (const float4*)(X + (long long)grow * DD + hf * 64);
            char* d = smem + AB + row * 256;
            const int r7 = row & 7;
#pragma unroll
            for (int q = 0; q < 8; q++) {
                float4 a = ok ? src[2 * q]     : make_float4(0, 0, 0, 0);
                float4 b = ok ? src[2 * q + 1] : make_float4(0, 0, 0, 0);
                uint4 v;
                v.x = packh2(a.x, a.y);
                v.y = packh2(a.z, a.w);
                v.z = packh2(b.x, b.y);
                v.w = packh2(b.z, b.w);
                *(uint4*)(d + (((8 * hf + q) ^ r7) << 4)) = v;
            }
        }

        // ---- Epilogue 2: h2 = relu(acc+b2) -> global fp16 ----
        {
            __half* H = (__half*)H2h;
            const int rowb = t * TILE + mg * 64;
#pragma unroll
            for (int mt = 0; mt < 4; mt++) {
                const int r0 = rowb + mt * 16 + (lane >> 2);
                const int r1 = r0 + 8;
                const bool ok0 = r0 < N, ok1 = r1 < N;
#pragma unroll
                for (int nt = 0; nt < 4; nt++) {
                    const int cc = ng * 32 + nt * 8 + (lane & 3) * 2;
                    const float bx = sB2[cc], by = sB2[cc + 1];
                    if (ok0) {
                        __half2 v = __floats2half2_rn(
                            fmaxf(acc[mt][nt][0] + bx, 0.f),
                            fmaxf(acc[mt][nt][1] + by, 0.f));
                        *(__half2*)(H + (long long)r0 * DD + cc) = v;
                    }
                    if (ok1) {
                        __half2 v = __floats2half2_rn(
                            fmaxf(acc[mt][nt][2] + bx, 0.f),
                            fmaxf(acc[mt][nt][3] + by, 0.f));
                        *(__half2*)(H + (long long)r1 * DD + cc) = v;
                    }
                }
            }
        }
        GBAR(g);
    }
}

// ---------------------------------------------------------------------------
// Edge decode (R9): 16 lanes per edge, 4 edges per warp, uint4 loads.
// ---------------------------------------------------------------------------
__device__ __forceinline__ float dot16B(uint4 a, uint4 b) {
    float2 s0 = __half22float2(*(const __half2*)&a.x);
    float2 t0 = __half22float2(*(const __half2*)&b.x);
    float2 s1 = __half22float2(*(const __half2*)&a.y);
    float2 t1 = __half22float2(*(const __half2*)&b.y);
    float2 s2 = __half22float2(*(const __half2*)&a.z);
    float2 t2 = __half22float2(*(const __half2*)&b.z);
    float2 s3 = __half22float2(*(const __half2*)&a.w);
    float2 t3 = __half22float2(*(const __half2*)&b.w);
    float r = s0.x * t0.x;
    r = fmaf(s0.y, t0.y, r);
    r = fmaf(s1.x, t1.x, r);
    r = fmaf(s1.y, t1.y, r);
    r = fmaf(s2.x, t2.x, r);
    r = fmaf(s2.y, t2.y, r);
    r = fmaf(s3.x, t3.x, r);
    r = fmaf(s3.y, t3.y, r);
    return r;
}

__global__ void __launch_bounds__(256) edge_dot_kernel(
    const uint4* __restrict__ H16,
    const int* __restrict__ edge_index,
    const int* __restrict__ lbl,
    float* __restrict__ out,
    float* __restrict__ lblout,
    int E, int N)
{
    const int gwarp = (blockIdx.x * blockDim.x + threadIdx.x) >> 5;
    const int lane  = threadIdx.x & 31;
    const int el = lane & 15;
    const int eh = lane >> 4;
    const int base = gwarp * 4;
    if (base >= E) return;

    const int eA = base + eh;
    const int eB = base + eh + 2;
    const bool okA = eA < E, okB = eB < E;
    const int iA = okA ? eA : 0;
    const int iB = okB ? eB : 0;

    int sA = edge_index[iA], dA = edge_index[E + iA];
    int sB = edge_index[iB], dB = edge_index[E + iB];
    sA = min(max(sA, 0), N - 1); dA = min(max(dA, 0), N - 1);
    sB = min(max(sB, 0), N - 1); dB = min(max(dB, 0), N - 1);

    const uint4 vsA = H16[sA * 16 + el];
    const uint4 vdA = H16[dA * 16 + el];
    const uint4 vsB = H16[sB * 16 + el];
    const uint4 vdB = H16[dB * 16 + el];

    float rA = dot16B(vsA, vdA);
    float rB = dot16B(vsB, vdB);

#pragma unroll
    for (int o = 8; o > 0; o >>= 1) {
        rA += __shfl_xor_sync(0xFFFFFFFFu, rA, o);
        rB += __shfl_xor_sync(0xFFFFFFFFu, rB, o);
    }

    if (el == 0) {
        if (okA) out[eA] = rA;
        if (okB) out[eB] = rB;
    }
    if (lblout && el == 1) {
        if (okA) lblout[eA] = (float)lbl[eA];
        if (okB) lblout[eB] = (float)lbl[eB];
    }
}

extern "C" void kernel_launch(void* const* d_in, const int* in_sizes, int n_in,
                              void* d_out, int out_size)
{
    const float* x   = (const float*)d_in[0];
    const int*   ei  = (const int*)d_in[1];
    const int*   lbl = (const int*)d_in[2];
    const float* W1  = (const float*)d_in[3];
    const float* b1  = (const float*)d_in[4];
    const float* W2  = (const float*)d_in[5];
    const float* b2  = (const float*)d_in[6];

    int N = in_sizes[0] / DD;   // 100000
    int E = in_sizes[2];        // 500000

    uint4* h2h;
    __half *w1h, *w2h;
    cudaGetSymbolAddress((void**)&h2h, g_h2h);
    cudaGetSymbolAddress((void**)&w1h, g_w1h);
    cudaGetSymbolAddress((void**)&w2h, g_w2h);

    cudaFuncSetAttribute(mlp_fused_kernel,
                         cudaFuncAttributeMaxDynamicSharedMemorySize, SMEM_TOTAL);

    wprep_kernel<<<(2 * DD * DD + 255) / 256, 256>>>(W1, W2, w1h, w2h);

    int T = (N + TILE - 1) / TILE;
    mlp_fused_kernel<<<NSM, 512, SMEM_TOTAL>>>(x, w1h, w2h, b1, b2, h2h, N, T);

    float* out = (float*)d_out;
    float* lblout = (out_size >= 2 * E) ? out + E : nullptr;
    int warps  = (E + 3) / 4;            // 4 edges per warp
    int blocks = (warps + 7) / 8;        // 8 warps per block
    edge_dot_kernel<<<blocks, 256>>>(h2h, ei, lbl, out, lblout, E, N);
}

// round 12
// speedup vs baseline: 4.7379x; 1.0458x over previous
#include <cuda_runtime.h>
#include <cuda_fp16.h>
#include <cstdint>

// ---------------------------------------------------------------------------
// GNNTransductiveEdgeHead, R12:
//  - MLP: persistent CTA, two 8-warp streams, 128-row tiles, fp16 GEMM
//    (fp32 accum). W converted fp32->fp16 in-kernel (wprep launch deleted).
//  - edge dot: 16 lanes/edge, 4 edges/warp, half2-math dot (issue cut).
// ---------------------------------------------------------------------------

#define DD 128
#define TILE 128           // rows per stream-tile
#define MAX_NODES 100000
#define NSM 148

// SMEM layout (bytes): rows are 128 fp16 = 256B, XOR-swizzled 16B chunks.
#define P_W1H 0
#define P_W2H 32768
#define A_BASE 65536       // stream g: A_BASE + g*32768
#define B1_OFF 131072
#define B2_OFF 131584
#define SMEM_TOTAL 132096

__device__ uint4 g_h2h[MAX_NODES * 16];          // h2 as fp16, 256B per node

__device__ __forceinline__ uint32_t smem_u32(const void* p) {
    uint32_t a;
    asm("{ .reg .u64 t; cvta.to.shared.u64 t, %1; cvt.u32.u64 %0, t; }"
        : "=r"(a) : "l"(p));
    return a;
}
__device__ __forceinline__ void ldmatrix_x4(uint32_t& r0, uint32_t& r1,
                                            uint32_t& r2, uint32_t& r3,
                                            uint32_t addr) {
    asm volatile("ldmatrix.sync.aligned.m8n8.x4.shared.b16 {%0,%1,%2,%3}, [%4];"
                 : "=r"(r0), "=r"(r1), "=r"(r2), "=r"(r3) : "r"(addr));
}
__device__ __forceinline__ void ldmatrix_x4_trans(uint32_t& r0, uint32_t& r1,
                                                  uint32_t& r2, uint32_t& r3,
                                                  uint32_t addr) {
    asm volatile("ldmatrix.sync.aligned.m8n8.x4.trans.shared.b16 {%0,%1,%2,%3}, [%4];"
                 : "=r"(r0), "=r"(r1), "=r"(r2), "=r"(r3) : "r"(addr));
}
__device__ __forceinline__ void mma_f16(float* c, const uint32_t* a,
                                        uint32_t b0, uint32_t b1) {
    asm volatile(
        "mma.sync.aligned.m16n8k16.row.col.f32.f16.f16.f32 "
        "{%0,%1,%2,%3}, {%4,%5,%6,%7}, {%8,%9}, {%0,%1,%2,%3};"
        : "+f"(c[0]), "+f"(c[1]), "+f"(c[2]), "+f"(c[3])
        : "r"(a[0]), "r"(a[1]), "r"(a[2]), "r"(a[3]), "r"(b0), "r"(b1));
}
__device__ __forceinline__ uint32_t packh2(float x, float y) {
    __half2 h = __floats2half2_rn(x, y);
    return *(uint32_t*)&h;
}
#define GBAR(gid) asm volatile("bar.sync %0, %1;" :: "r"((gid) + 1), "r"(256) : "memory")

// fp16 MMA over one staged A tile vs one W panel: 8 ks x (6 LDSM + 16 HMMA).
__device__ __forceinline__ void mma_layer(float acc[4][4][4],
                                          uint32_t aB, uint32_t pB,
                                          int hA, int x7, int ng) {
#pragma unroll
    for (int ks = 0; ks < 8; ks++) {
        uint32_t ah[4][4];
#pragma unroll
        for (int mt = 0; mt < 4; mt++) {
            const uint32_t off = mt * 4096 + ((((2 * ks + hA) ^ x7)) << 4);
            ldmatrix_x4(ah[mt][0], ah[mt][1], ah[mt][2], ah[mt][3], aB + off);
        }
        uint32_t bh[4][2];
#pragma unroll
        for (int hf = 0; hf < 2; hf++) {
            const uint32_t off = ks * 4096 +
                ((((4 * ng + 2 * hf + hA) ^ x7)) << 4);
            uint32_t r0, r1, r2, r3;
            ldmatrix_x4_trans(r0, r1, r2, r3, pB + off);
            bh[2 * hf][0] = r0; bh[2 * hf][1] = r1;
            bh[2 * hf + 1][0] = r2; bh[2 * hf + 1][1] = r3;
        }
#pragma unroll
        for (int mt = 0; mt < 4; mt++)
#pragma unroll
            for (int nt = 0; nt < 4; nt++)
                mma_f16(acc[mt][nt], ah[mt], bh[nt][0], bh[nt][1]);
    }
}

// ---------------------------------------------------------------------------
// Persistent fused MLP: 512 thr = 2 streams x 8 warps; stream tile 128 rows;
// warp (mg=w&1, ng=w>>1) owns rows [64mg,64mg+64) x cols [32ng,32ng+32).
// W converted fp32->fp16 during prologue staging (no wprep kernel).
// ---------------------------------------------------------------------------
__global__ void __launch_bounds__(512, 1) mlp_fused_kernel(
    const float* __restrict__ X,
    const float* __restrict__ W1, const float* __restrict__ W2,
    const float* __restrict__ bias1, const float* __restrict__ bias2,
    uint4* __restrict__ H2h,
    int N, int T)
{
    extern __shared__ __align__(16) char smem[];
    const uint32_t sb = smem_u32(smem);
    const int tid  = threadIdx.x;
    const int g    = tid >> 8;        // stream 0/1
    const int tg   = tid & 255;
    const int warp = tg >> 5;
    const int lane = tid & 31;
    const int mg = warp & 1;
    const int ng = warp >> 1;

    // --- Prologue: load W fp32, convert to fp16, store swizzled ---
    {
        const float* wsrc[2] = {W1, W2};
        const uint32_t pdst[2] = {P_W1H, P_W2H};
#pragma unroll
        for (int i = 0; i < 8; i++) {
            int idx = tid + i * 512;          // 4096 chunks (16B fp16 each)
            int panel = idx >> 11;
            int rem   = idx & 2047;
            int row   = rem >> 4;
            int c     = rem & 15;             // chunk = 8 cols
            const float4* s = (const float4*)(wsrc[panel] + row * DD + c * 8);
            const float4 a = s[0], b = s[1];
            uint4 v;
            v.x = packh2(a.x, a.y);
            v.y = packh2(a.z, a.w);
            v.z = packh2(b.x, b.y);
            v.w = packh2(b.z, b.w);
            *(uint4*)(smem + pdst[panel] + row * 256 +
                      ((c ^ (row & 7)) << 4)) = v;
        }
    }
    if (tid < DD) {
        ((float*)(smem + B1_OFF))[tid] = bias1[tid];
        ((float*)(smem + B2_OFF))[tid] = bias2[tid];
    }

    const uint32_t AB = A_BASE + g * 32768;

    // Stage first tile: thread owns row tg>>1, 64-float half (tg&1).
    int t = 2 * blockIdx.x + g;
    if (t < T) {
        const int row = tg >> 1, hf = tg & 1;
        const int grow = t * TILE + row;
        const bool ok = grow < N;
        const float4* src = (const float4*)(X + (long long)grow * DD + hf * 64);
        char* d = smem + AB + row * 256;
        const int r7 = row & 7;
#pragma unroll
        for (int q = 0; q < 8; q++) {
            float4 a = ok ? src[2 * q]     : make_float4(0, 0, 0, 0);
            float4 b = ok ? src[2 * q + 1] : make_float4(0, 0, 0, 0);
            uint4 v;
            v.x = packh2(a.x, a.y);
            v.y = packh2(a.z, a.w);
            v.z = packh2(b.x, b.y);
            v.w = packh2(b.z, b.w);
            *(uint4*)(d + (((8 * hf + q) ^ r7) << 4)) = v;
        }
    }
    __syncthreads();   // W panels + first tiles visible

    const int hA = lane >> 4;
    const int x7 = lane & 7;
    const uint32_t aRow = (uint32_t)(mg * 64 + (lane & 15));
    const uint32_t aB = sb + AB + aRow * 256;
    const uint32_t bRow = (uint32_t)(lane & 15) * 256;
    const uint32_t p1 = sb + P_W1H + bRow;
    const uint32_t p2 = sb + P_W2H + bRow;
    const float* sB1 = (const float*)(smem + B1_OFF);
    const float* sB2 = (const float*)(smem + B2_OFF);

    for (; t < T; t += 2 * NSM) {
        const int tn = t + 2 * NSM;
        const bool have_next = tn < T;

        float acc[4][4][4];
#pragma unroll
        for (int mt = 0; mt < 4; mt++)
#pragma unroll
            for (int nt = 0; nt < 4; nt++)
#pragma unroll
                for (int c = 0; c < 4; c++) acc[mt][nt][c] = 0.f;

        // ---- Layer 1 MMAs ----
        mma_layer(acc, aB, p1, hA, x7, ng);
        GBAR(g);   // stream done reading A

        // ---- Epilogue 1: h1 = relu(acc+b1) -> fp16 A buffer ----
#pragma unroll
        for (int mt = 0; mt < 4; mt++) {
            const int r0 = mg * 64 + mt * 16 + (lane >> 2);
            const int r1 = r0 + 8;
#pragma unroll
            for (int nt = 0; nt < 4; nt++) {
                const int cc = ng * 32 + nt * 8 + (lane & 3) * 2;
                const float bx = sB1[cc], by = sB1[cc + 1];
                const uint32_t w0 = ((4 * ng + nt) ^ (r0 & 7)) * 16 + 4 * (lane & 3);
                const uint32_t w1 = ((4 * ng + nt) ^ (r1 & 7)) * 16 + 4 * (lane & 3);
                *(uint32_t*)(smem + AB + r0 * 256 + w0) =
                    packh2(fmaxf(acc[mt][nt][0] + bx, 0.f),
                           fmaxf(acc[mt][nt][1] + by, 0.f));
                *(uint32_t*)(smem + AB + r1 * 256 + w1) =
                    packh2(fmaxf(acc[mt][nt][2] + bx, 0.f),
                           fmaxf(acc[mt][nt][3] + by, 0.f));
            }
        }
        GBAR(g);   // h1 visible

        // ---- Layer 2 MMAs ----
#pragma unroll
        for (int mt = 0; mt < 4; mt++)
#pragma unroll
            for (int nt = 0; nt < 4; nt++)
#pragma unroll
                for (int c = 0; c < 4; c++) acc[mt][nt][c] = 0.f;
        mma_layer(acc, aB, p2, hA, x7, ng);
        GBAR(g);   // A free for restage

        // ---- Stage next tile ----
        if (have_next) {
            const int row = tg >> 1, hf = tg & 1;
            const int grow = tn * TILE + row;
            const bool ok = grow < N;
            const float4* src =
                (const float4*)(X + (long long)grow * DD + hf * 64);
            char* d = smem + AB + row * 256;
            const int r7 = row & 7;
#pragma unroll
            for (int q = 0; q < 8; q++) {
                float4 a = ok ? src[2 * q]     : make_float4(0, 0, 0, 0);
                float4 b = ok ? src[2 * q + 1] : make_float4(0, 0, 0, 0);
                uint4 v;
                v.x = packh2(a.x, a.y);
                v.y = packh2(a.z, a.w);
                v.z = packh2(b.x, b.y);
                v.w = packh2(b.z, b.w);
                *(uint4*)(d + (((8 * hf + q) ^ r7) << 4)) = v;
            }
        }

        // ---- Epilogue 2: h2 = relu(acc+b2) -> global fp16 ----
        {
            __half* H = (__half*)H2h;
            const int rowb = t * TILE + mg * 64;
#pragma unroll
            for (int mt = 0; mt < 4; mt++) {
                const int r0 = rowb + mt * 16 + (lane >> 2);
                const int r1 = r0 + 8;
                const bool ok0 = r0 < N, ok1 = r1 < N;
#pragma unroll
                for (int nt = 0; nt < 4; nt++) {
                    const int cc = ng * 32 + nt * 8 + (lane & 3) * 2;
                    const float bx = sB2[cc], by = sB2[cc + 1];
                    if (ok0) {
                        __half2 v = __floats2half2_rn(
                            fmaxf(acc[mt][nt][0] + bx, 0.f),
                            fmaxf(acc[mt][nt][1] + by, 0.f));
                        *(__half2*)(H + (long long)r0 * DD + cc) = v;
                    }
                    if (ok1) {
                        __half2 v = __floats2half2_rn(
                            fmaxf(acc[mt][nt][2] + bx, 0.f),
                            fmaxf(acc[mt][nt][3] + by, 0.f));
                        *(__half2*)(H + (long long)r1 * DD + cc) = v;
                    }
                }
            }
        }
        GBAR(g);
    }
}

// ---------------------------------------------------------------------------
// Edge decode: 16 lanes/edge, 4 edges/warp, half2-math dot.
// Two half2 accumulators per 16B chunk (2 products/slot -> tiny fp16 error).
// ---------------------------------------------------------------------------
__device__ __forceinline__ float dot16B(uint4 a, uint4 b) {
    __half2 p0 = __hmul2(*(const __half2*)&a.x, *(const __half2*)&b.x);
    p0 = __hfma2(*(const __half2*)&a.z, *(const __half2*)&b.z, p0);
    __half2 p1 = __hmul2(*(const __half2*)&a.y, *(const __half2*)&b.y);
    p1 = __hfma2(*(const __half2*)&a.w, *(const __half2*)&b.w, p1);
    const float2 f0 = __half22float2(p0);
    const float2 f1 = __half22float2(p1);
    return (f0.x + f0.y) + (f1.x + f1.y);
}

__global__ void __launch_bounds__(256) edge_dot_kernel(
    const uint4* __restrict__ H16,
    const int* __restrict__ edge_index,
    const int* __restrict__ lbl,
    float* __restrict__ out,
    float* __restrict__ lblout,
    int E, int N)
{
    const int gwarp = (blockIdx.x * blockDim.x + threadIdx.x) >> 5;
    const int lane  = threadIdx.x & 31;
    const int el = lane & 15;
    const int eh = lane >> 4;
    const int base = gwarp * 4;
    if (base >= E) return;

    const int eA = base + eh;
    const int eB = base + eh + 2;
    const bool okA = eA < E, okB = eB < E;
    const int iA = okA ? eA : 0;
    const int iB = okB ? eB : 0;

    int sA = edge_index[iA], dA = edge_index[E + iA];
    int sB = edge_index[iB], dB = edge_index[E + iB];
    sA = min(max(sA, 0), N - 1); dA = min(max(dA, 0), N - 1);
    sB = min(max(sB, 0), N - 1); dB = min(max(dB, 0), N - 1);

    const uint4 vsA = H16[sA * 16 + el];
    const uint4 vdA = H16[dA * 16 + el];
    const uint4 vsB = H16[sB * 16 + el];
    const uint4 vdB = H16[dB * 16 + el];

    float rA = dot16B(vsA, vdA);
    float rB = dot16B(vsB, vdB);

#pragma unroll
    for (int o = 8; o > 0; o >>= 1) {
        rA += __shfl_xor_sync(0xFFFFFFFFu, rA, o);
        rB += __shfl_xor_sync(0xFFFFFFFFu, rB, o);
    }

    if (el == 0) {
        if (okA) out[eA] = rA;
        if (okB) out[eB] = rB;
    }
    if (lblout && el == 1) {
        if (okA) lblout[eA] = (float)lbl[eA];
        if (okB) lblout[eB] = (float)lbl[eB];
    }
}

extern "C" void kernel_launch(void* const* d_in, const int* in_sizes, int n_in,
                              void* d_out, int out_size)
{
    const float* x   = (const float*)d_in[0];
    const int*   ei  = (const int*)d_in[1];
    const int*   lbl = (const int*)d_in[2];
    const float* W1  = (const float*)d_in[3];
    const float* b1  = (const float*)d_in[4];
    const float* W2  = (const float*)d_in[5];
    const float* b2  = (const float*)d_in[6];

    int N = in_sizes[0] / DD;   // 100000
    int E = in_sizes[2];        // 500000

    uint4* h2h;
    cudaGetSymbolAddress((void**)&h2h, g_h2h);

    cudaFuncSetAttribute(mlp_fused_kernel,
                         cudaFuncAttributeMaxDynamicSharedMemorySize, SMEM_TOTAL);

    int T = (N + TILE - 1) / TILE;
    mlp_fused_kernel<<<NSM, 512, SMEM_TOTAL>>>(x, W1, W2, b1, b2, h2h, N, T);

    float* out = (float*)d_out;
    float* lblout = (out_size >= 2 * E) ? out + E : nullptr;
    int warps  = (E + 3) / 4;            // 4 edges per warp
    int blocks = (warps + 7) / 8;        // 8 warps per block
    edge_dot_kernel<<<blocks, 256>>>(h2h, ei, lbl, out, lblout, E, N);
}